// round 5
// baseline (speedup 1.0000x reference)
#include <cuda_runtime.h>
#include <cuda_bf16.h>
#include <math_constants.h>

// Problem constants
#define BATCH   8
#define SEQ     4096
#define DIM     256
#define HEADS   8
#define HD      32
#define NFREQ   17          // HD/2 + 1
#define ROWS    (BATCH*SEQ) // 32768
#define BH      (BATCH*HEADS) // 64

typedef unsigned long long u64;

// ---------------- scratch (static __device__ — no allocations allowed) ----------------
__device__ float  g_lin[3][(size_t)ROWS * DIM];            // ql, kl, vl
__device__ float2 g_QK[2][(size_t)BH * NFREQ * SEQ];       // Qhat, Khat (seq-major per (b,h,f))
__device__ float2 g_P[(size_t)BH * NFREQ * SEQ];           // product after inverse seq-FFT

// ---------------- packed fp32x2 helpers (sm_100+ only; ptxas never auto-fuses) -------
__device__ __forceinline__ u64 pack2(float lo, float hi) {
    u64 r; asm("mov.b64 %0, {%1,%2};" : "=l"(r) : "f"(lo), "f"(hi)); return r;
}
__device__ __forceinline__ void unpack2(u64 v, float &lo, float &hi) {
    asm("mov.b64 {%0,%1}, %2;" : "=f"(lo), "=f"(hi) : "l"(v));
}
__device__ __forceinline__ void ffma2(u64 &d, u64 a, u64 b) {
    asm("fma.rn.f32x2 %0, %1, %2, %0;" : "+l"(d) : "l"(a), "l"(b));
}

// =====================================================================================
// Kernel 1: fused QKV GEMM   out[i,j] = sum_k X[i,k] * W[j,k] + b[j]
// BM=128 BN=128 BK=16, 256 threads. Microtile 8(M)x8(N) computed as 4 packed M-pairs
// x 8 N via fma.rn.f32x2 — halves FFMA issue slots vs scalar FFMA.
// =====================================================================================
__global__ __launch_bounds__(256) void gemm_qkv(
    const float* __restrict__ q, const float* __restrict__ k, const float* __restrict__ v,
    const float* __restrict__ Wq, const float* __restrict__ bq,
    const float* __restrict__ Wk, const float* __restrict__ bk,
    const float* __restrict__ Wv, const float* __restrict__ bv)
{
    const int z = blockIdx.z;
    const float* X    = (z == 0) ? q  : (z == 1) ? k  : v;
    const float* W    = (z == 0) ? Wq : (z == 1) ? Wk : Wv;
    const float* bias = (z == 0) ? bq : (z == 1) ? bk : bv;
    float* out = g_lin[z];

    __shared__ float As[16][128];   // [k][m]  (m contiguous -> M-pairs are u64-aligned)
    __shared__ float Bs[16][128];   // [k][n]

    const int tid  = threadIdx.x;
    const int tx   = tid & 15;      // 0..15 (N dir)
    const int ty   = tid >> 4;      // 0..15 (M dir)
    const int row0 = blockIdx.x * 128;
    const int col0 = blockIdx.y * 128;

    u64 acc2[4][8];                 // [m-pair][n], packed {row 2p, row 2p+1}
#pragma unroll
    for (int i = 0; i < 4; i++)
#pragma unroll
        for (int j = 0; j < 8; j++) acc2[i][j] = 0ULL;

    const int ar  = tid >> 2;          // 0..63
    const int ac  = (tid & 3) << 2;    // 0,4,8,12
    const int bc  = tid >> 1;          // 0..127
    const int bk0 = (tid & 1) << 3;    // 0 or 8

    for (int kk = 0; kk < DIM; kk += 16) {
        // load A tile (128 rows x 16 k)
#pragma unroll
        for (int r2 = 0; r2 < 128; r2 += 64) {
            float4 av = *reinterpret_cast<const float4*>(
                &X[(size_t)(row0 + ar + r2) * DIM + kk + ac]);
            As[ac + 0][ar + r2] = av.x;
            As[ac + 1][ar + r2] = av.y;
            As[ac + 2][ar + r2] = av.z;
            As[ac + 3][ar + r2] = av.w;
        }
        // load B tile (128 cols x 16 k): Bs[k'][col] = W[(col0+col)*DIM + kk + k']
        {
            const float* wrow = &W[(size_t)(col0 + bc) * DIM + kk + bk0];
            float4 b0 = *reinterpret_cast<const float4*>(wrow);
            float4 b1 = *reinterpret_cast<const float4*>(wrow + 4);
            Bs[bk0 + 0][bc] = b0.x; Bs[bk0 + 1][bc] = b0.y;
            Bs[bk0 + 2][bc] = b0.z; Bs[bk0 + 3][bc] = b0.w;
            Bs[bk0 + 4][bc] = b1.x; Bs[bk0 + 5][bc] = b1.y;
            Bs[bk0 + 6][bc] = b1.z; Bs[bk0 + 7][bc] = b1.w;
        }
        __syncthreads();
#pragma unroll
        for (int kq = 0; kq < 16; kq++) {
            // A: 4 packed M-pairs, loaded directly as 64-bit from SMEM
            const u64* arow = reinterpret_cast<const u64*>(&As[kq][ty * 8]);
            u64 ap0 = arow[0], ap1 = arow[1], ap2 = arow[2], ap3 = arow[3];
            // B: 8 scalars, broadcast-packed {b,b}
            float4 b0 = *reinterpret_cast<const float4*>(&Bs[kq][tx * 8]);
            float4 b1 = *reinterpret_cast<const float4*>(&Bs[kq][tx * 8 + 4]);
            u64 bp[8];
            bp[0] = pack2(b0.x, b0.x); bp[1] = pack2(b0.y, b0.y);
            bp[2] = pack2(b0.z, b0.z); bp[3] = pack2(b0.w, b0.w);
            bp[4] = pack2(b1.x, b1.x); bp[5] = pack2(b1.y, b1.y);
            bp[6] = pack2(b1.z, b1.z); bp[7] = pack2(b1.w, b1.w);
#pragma unroll
            for (int j = 0; j < 8; j++) {
                ffma2(acc2[0][j], ap0, bp[j]);
                ffma2(acc2[1][j], ap1, bp[j]);
                ffma2(acc2[2][j], ap2, bp[j]);
                ffma2(acc2[3][j], ap3, bp[j]);
            }
        }
        __syncthreads();
    }

    float br[8];
#pragma unroll
    for (int j = 0; j < 8; j++) br[j] = bias[col0 + tx * 8 + j];

#pragma unroll
    for (int ip = 0; ip < 4; ip++) {
        float lo[8], hi[8];
#pragma unroll
        for (int j = 0; j < 8; j++) unpack2(acc2[ip][j], lo[j], hi[j]);
        int r0 = row0 + ty * 8 + 2 * ip;
        float* orow0 = &out[(size_t)r0 * DIM + col0 + tx * 8];
        float* orow1 = orow0 + DIM;
        *reinterpret_cast<float4*>(orow0) =
            make_float4(lo[0] + br[0], lo[1] + br[1], lo[2] + br[2], lo[3] + br[3]);
        *reinterpret_cast<float4*>(orow0 + 4) =
            make_float4(lo[4] + br[4], lo[5] + br[5], lo[6] + br[6], lo[7] + br[7]);
        *reinterpret_cast<float4*>(orow1) =
            make_float4(hi[0] + br[0], hi[1] + br[1], hi[2] + br[2], hi[3] + br[3]);
        *reinterpret_cast<float4*>(orow1 + 4) =
            make_float4(hi[4] + br[4], hi[5] + br[5], hi[6] + br[6], hi[7] + br[7]);
    }
}

// =====================================================================================
// Kernel 2: rfft over head_dim (32 -> 17 complex bins) for ql and kl.
// 32 tokens per CTA, thread = (token, head). Output layout [bh][f][n] (seq-contiguous).
// =====================================================================================
__global__ __launch_bounds__(256) void rfft_heads()
{
    const int which = blockIdx.y;            // 0 -> Q, 1 -> K
    const float* __restrict__ src = g_lin[which];
    float2* __restrict__ dst = g_QK[which];

    __shared__ float xs[32 * 264];           // padded rows: head h at h*33
    __shared__ float twc[32], tws[32];       // cos/sin(2*pi*k/32)

    const int tid = threadIdx.x;
    if (tid < 32) {
        float s, c;
        sincospif((float)tid * (1.0f / 16.0f), &s, &c);
        twc[tid] = c; tws[tid] = s;
    }
    const int row0 = blockIdx.x * 32;
    for (int i = tid; i < 32 * 256; i += 256) {
        int tok = i >> 8, cc = i & 255;
        xs[tok * 264 + (cc >> 5) * 33 + (cc & 31)] = src[(size_t)row0 * DIM + i];
    }
    __syncthreads();

    const int tok = tid >> 3, h = tid & 7;
    float xr[32];
#pragma unroll
    for (int d = 0; d < 32; d++) xr[d] = xs[tok * 264 + h * 33 + d];

    const int b  = row0 >> 12;
    const int n  = (row0 & (SEQ - 1)) + tok;
    const int bh = b * HEADS + h;

    for (int f = 0; f < NFREQ; f++) {
        float re = 0.0f, im = 0.0f;
#pragma unroll
        for (int d = 0; d < 32; d++) {
            int k2 = (f * d) & 31;
            re = fmaf(xr[d], twc[k2], re);
            im = fmaf(xr[d], -tws[k2], im);
        }
        dst[((size_t)bh * NFREQ + f) * SEQ + n] = make_float2(re, im);
    }
}

// =====================================================================================
// Kernel 3: per (b,h,f) column: FFT4096(Q), FFT4096(K), pointwise mult (scaled),
// inverse FFT4096 -> g_P.  Stockham radix-2 in SMEM (no bit reversal).
// =====================================================================================
__device__ __forceinline__ void fftcore(float2* x, float2* y, const float2* tw,
                                        int tid, bool inv)
{
    float2* a = x; float2* b = y;
#pragma unroll 1
    for (int ls = 0; ls < 12; ls++) {
        const int s = 1 << ls;
#pragma unroll
        for (int t = tid; t < 2048; t += 256) {
            int p = t >> ls;
            int qq = t & (s - 1);
            float2 w = tw[p << ls];
            float wy = inv ? -w.y : w.y;
            float2 u = a[t];
            float2 v = a[t + 2048];
            float2 sum = make_float2(u.x + v.x, u.y + v.y);
            float2 dif = make_float2(u.x - v.x, u.y - v.y);
            int o = qq + (p << (ls + 1));
            b[o]     = sum;
            b[o + s] = make_float2(dif.x * w.x - dif.y * wy,
                                   dif.x * wy  + dif.y * w.x);
        }
        __syncthreads();
        float2* tmp = a; a = b; b = tmp;
    }
    // 12 stages (even) -> result back in x
}

__global__ __launch_bounds__(256) void fft_conv()
{
    extern __shared__ unsigned char smraw[];
    float2* tw = reinterpret_cast<float2*>(smraw);   // 2048
    float2* bq = tw + 2048;                          // 4096 (Qhat)
    float2* ba = bq + 4096;                          // 4096 work A
    float2* bb = ba + 4096;                          // 4096 work B

    const int tid = threadIdx.x;
    const int f   = blockIdx.x;      // 0..16
    const int bh  = blockIdx.y;      // 0..63
    const size_t base = ((size_t)bh * NFREQ + f) * SEQ;

    for (int i = tid; i < 2048; i += 256) {
        float s, c;
        sincospif((float)i * (1.0f / 2048.0f), &s, &c);
        tw[i] = make_float2(c, -s);
    }
    for (int i = tid; i < 4096; i += 256) ba[i] = g_QK[0][base + i];
    __syncthreads();

    fftcore(ba, bb, tw, tid, false);                 // Qhat in ba
    for (int i = tid; i < 4096; i += 256) bq[i] = ba[i];
    __syncthreads();

    for (int i = tid; i < 4096; i += 256) ba[i] = g_QK[1][base + i];
    __syncthreads();
    fftcore(ba, bb, tw, tid, false);                 // Khat in ba

    const float scale = 1.0f / 131072.0f;            // 1/(4096*32): both inverse norms
    for (int i = tid; i < 4096; i += 256) {
        float2 a = ba[i], q2 = bq[i];
        ba[i] = make_float2((a.x * q2.x - a.y * q2.y) * scale,
                            (a.x * q2.y + a.y * q2.x) * scale);
    }
    __syncthreads();
    fftcore(ba, bb, tw, tid, true);                  // inverse -> ba

    for (int i = tid; i < 4096; i += 256) g_P[base + i] = ba[i];
}

// =====================================================================================
// Kernel 4: irfft-32 over heads + softmax(32) + value gate + residual + LayerNorm(256)
// 32 tokens per CTA; warp handles 4 tokens; lane = head_dim index d.
// =====================================================================================
__global__ __launch_bounds__(256) void epilogue(
    const float* __restrict__ vin, const float* __restrict__ gamma,
    const float* __restrict__ beta, float* __restrict__ out)
{
    __shared__ float2 Psm[HEADS * NFREQ * 32];   // [h][f][tok]
    __shared__ float c32[32], s32[32];

    const int tid = threadIdx.x;
    if (tid < 32) {
        float s, c;
        sincospif((float)tid * (1.0f / 16.0f), &s, &c);
        c32[tid] = c; s32[tid] = s;
    }
    const int row0 = blockIdx.x * 32;
    const int b = row0 >> 12, n0 = row0 & (SEQ - 1);

    for (int i = tid; i < HEADS * NFREQ * 32; i += 256) {
        int h = i / (NFREQ * 32);
        int r = i - h * (NFREQ * 32);
        int f = r >> 5, tok = r & 31;
        Psm[i] = g_P[(((size_t)(b * HEADS + h)) * NFREQ + f) * SEQ + n0 + tok];
    }
    __syncthreads();

    const int w = tid >> 5, d = tid & 31;
    const float* __restrict__ vl = g_lin[2];

    for (int it = 0; it < 4; it++) {
        const int tok = w + it * 8;
        const int row = row0 + tok;
        float gh[8];
        float s1 = 0.0f, s2 = 0.0f;
#pragma unroll
        for (int h = 0; h < 8; h++) {
            const float2* Ph = &Psm[h * NFREQ * 32 + tok];
            float acc = Ph[0].x;                       // f = 0 (real)
            float2 F16 = Ph[16 * 32];
            acc += (d & 1) ? -F16.x : F16.x;           // Nyquist (real)
#pragma unroll
            for (int f = 1; f <= 15; f++) {
                float2 F = Ph[f * 32];
                int k2 = (f * d) & 31;
                acc += 2.0f * (F.x * c32[k2] - F.y * s32[k2]);
            }
            // softmax over 32 lanes
            float m = acc;
#pragma unroll
            for (int o = 16; o; o >>= 1) m = fmaxf(m, __shfl_xor_sync(0xffffffffu, m, o));
            float e = __expf(acc - m);
            float ss = e;
#pragma unroll
            for (int o = 16; o; o >>= 1) ss += __shfl_xor_sync(0xffffffffu, ss, o);
            float p = e / ss;
            int c = h * 32 + d;
            float vv = vl[(size_t)row * DIM + c];
            float rv = vin[(size_t)row * DIM + c];
            float g = fmaf(vv, p, rv);                 // gate + residual
            gh[h] = g; s1 += g; s2 = fmaf(g, g, s2);
        }
#pragma unroll
        for (int o = 16; o; o >>= 1) {
            s1 += __shfl_xor_sync(0xffffffffu, s1, o);
            s2 += __shfl_xor_sync(0xffffffffu, s2, o);
        }
        float mean = s1 * (1.0f / 256.0f);
        float var  = s2 * (1.0f / 256.0f) - mean * mean;
        float inv  = rsqrtf(var + 1e-5f);
#pragma unroll
        for (int h = 0; h < 8; h++) {
            int c = h * 32 + d;
            out[(size_t)row * DIM + c] = (gh[h] - mean) * inv * gamma[c] + beta[c];
        }
    }
}

// =====================================================================================
extern "C" void kernel_launch(void* const* d_in, const int* in_sizes, int n_in,
                              void* d_out, int out_size)
{
    const float* q     = (const float*)d_in[0];
    const float* k     = (const float*)d_in[1];
    const float* v     = (const float*)d_in[2];
    const float* Wq    = (const float*)d_in[3];
    const float* bq    = (const float*)d_in[4];
    const float* Wk    = (const float*)d_in[5];
    const float* bk    = (const float*)d_in[6];
    const float* Wv    = (const float*)d_in[7];
    const float* bv    = (const float*)d_in[8];
    const float* gamma = (const float*)d_in[9];
    const float* beta  = (const float*)d_in[10];
    float* out = (float*)d_out;

    const int fft_smem = (2048 + 3 * 4096) * (int)sizeof(float2);  // 114688 B
    cudaFuncSetAttribute(fft_conv, cudaFuncAttributeMaxDynamicSharedMemorySize, fft_smem);

    gemm_qkv<<<dim3(ROWS / 128, DIM / 128, 3), 256>>>(q, k, v, Wq, bq, Wk, bk, Wv, bv);
    rfft_heads<<<dim3(ROWS / 32, 2), 256>>>();
    fft_conv<<<dim3(NFREQ, BH), 256, fft_smem>>>();
    epilogue<<<ROWS / 32, 256>>>(v, gamma, beta, out);
}

// round 7
// speedup vs baseline: 1.1682x; 1.1682x over previous
#include <cuda_runtime.h>
#include <cuda_bf16.h>
#include <math_constants.h>
#include <cstdint>

// Problem constants
#define BATCH   8
#define SEQ     4096
#define DIM     256
#define HEADS   8
#define HD      32
#define NFREQ   17          // HD/2 + 1
#define ROWS    (BATCH*SEQ) // 32768
#define BH      (BATCH*HEADS) // 64

typedef unsigned long long u64;

// ---------------- scratch (static __device__ — no allocations allowed) ----------------
__device__ float  g_lin[3][(size_t)ROWS * DIM];            // ql, kl, vl
__device__ float2 g_QK[2][(size_t)BH * NFREQ * SEQ];       // Qhat, Khat (seq-major per (b,h,f))
__device__ float2 g_P[(size_t)BH * NFREQ * SEQ];           // product after inverse seq-FFT

// =====================================================================================
// Kernel 1: fused QKV GEMM via mma.sync (HMMA, base-arch PTX — tcgen05 is unavailable:
// harness ptxas targets compute_103, not 103a). bf16 hi/lo split, fp32 accumulate:
//   X*W^T ≈ Xhi*Whi + Xhi*Wlo + Xlo*Whi   (lo*lo dropped, ~2^-17 rel)
// CTA tile: M=256 x N=128, K chunks of 32. 8 warps = 4(M) x 2(N), warp tile 64x64.
// =====================================================================================
#define BM 256
#define BN 128
#define BK 32
#define ASTRIDE 36            // bf16 elements per SMEM row (32 + 4 pad; 72B = 8-aligned)

// dynamic smem layout (bytes)
#define SM_AHI 0
#define SM_ALO (BM * ASTRIDE * 2)                 // 18432
#define SM_BHI (2 * BM * ASTRIDE * 2)             // 36864
#define SM_BLO (2 * BM * ASTRIDE * 2 + BN * ASTRIDE * 2)   // 46080
#define SM_GEMM_TOTAL (2 * BM * ASTRIDE * 2 + 2 * BN * ASTRIDE * 2)  // 55296

__device__ __forceinline__ void cvt_hi_lo(float4 xv, u64& hw, u64& lw) {
    __nv_bfloat16 h0 = __float2bfloat16_rn(xv.x);
    __nv_bfloat16 h1 = __float2bfloat16_rn(xv.y);
    __nv_bfloat16 h2 = __float2bfloat16_rn(xv.z);
    __nv_bfloat16 h3 = __float2bfloat16_rn(xv.w);
    __nv_bfloat16 l0 = __float2bfloat16_rn(xv.x - __bfloat162float(h0));
    __nv_bfloat16 l1 = __float2bfloat16_rn(xv.y - __bfloat162float(h1));
    __nv_bfloat16 l2 = __float2bfloat16_rn(xv.z - __bfloat162float(h2));
    __nv_bfloat16 l3 = __float2bfloat16_rn(xv.w - __bfloat162float(h3));
    hw = (u64)__bfloat16_as_ushort(h0) | ((u64)__bfloat16_as_ushort(h1) << 16)
       | ((u64)__bfloat16_as_ushort(h2) << 32) | ((u64)__bfloat16_as_ushort(h3) << 48);
    lw = (u64)__bfloat16_as_ushort(l0) | ((u64)__bfloat16_as_ushort(l1) << 16)
       | ((u64)__bfloat16_as_ushort(l2) << 32) | ((u64)__bfloat16_as_ushort(l3) << 48);
}

__device__ __forceinline__ void mma16816(float* c, const uint32_t* a, const uint32_t* b) {
    asm volatile(
        "mma.sync.aligned.m16n8k16.row.col.f32.bf16.bf16.f32 "
        "{%0,%1,%2,%3}, {%4,%5,%6,%7}, {%8,%9}, {%0,%1,%2,%3};"
        : "+f"(c[0]), "+f"(c[1]), "+f"(c[2]), "+f"(c[3])
        : "r"(a[0]), "r"(a[1]), "r"(a[2]), "r"(a[3]), "r"(b[0]), "r"(b[1]));
}

__global__ __launch_bounds__(256) void gemm_qkv_mma(
    const float* __restrict__ q, const float* __restrict__ k, const float* __restrict__ v,
    const float* __restrict__ Wq, const float* __restrict__ bq,
    const float* __restrict__ Wk, const float* __restrict__ bk,
    const float* __restrict__ Wv, const float* __restrict__ bv)
{
    extern __shared__ unsigned char smem[];

    const int z = blockIdx.z;
    const float* X    = (z == 0) ? q  : (z == 1) ? k  : v;
    const float* W    = (z == 0) ? Wq : (z == 1) ? Wk : Wv;
    const float* bias = (z == 0) ? bq : (z == 1) ? bk : bv;
    float* out = g_lin[z];

    const int tid   = threadIdx.x;
    const int wid   = tid >> 5;
    const int lane  = tid & 31;
    const int group = lane >> 2;      // 0..7
    const int tig   = lane & 3;       // 0..3
    const int warpM = wid >> 1;       // 0..3
    const int warpN = wid & 1;        // 0..1
    const int row0  = blockIdx.x * BM;
    const int col0  = blockIdx.y * BN;

    const uint16_t* Ahi = reinterpret_cast<const uint16_t*>(smem + SM_AHI);
    const uint16_t* Alo = reinterpret_cast<const uint16_t*>(smem + SM_ALO);
    const uint16_t* Bhi = reinterpret_cast<const uint16_t*>(smem + SM_BHI);
    const uint16_t* Blo = reinterpret_cast<const uint16_t*>(smem + SM_BLO);

    float acc[4][8][4];
#pragma unroll
    for (int mi = 0; mi < 4; mi++)
#pragma unroll
        for (int ni = 0; ni < 8; ni++)
#pragma unroll
            for (int r = 0; r < 4; r++) acc[mi][ni][r] = 0.0f;

#pragma unroll 1
    for (int kk = 0; kk < DIM; kk += BK) {
        // ---- load + split A chunk: BM rows x BK k (one row per thread) ----
        {
            const float* xr = &X[(size_t)(row0 + tid) * DIM + kk];
            unsigned char* ah = smem + SM_AHI + tid * (ASTRIDE * 2);
            unsigned char* al = smem + SM_ALO + tid * (ASTRIDE * 2);
#pragma unroll
            for (int j = 0; j < 8; j++) {
                u64 hw, lw;
                cvt_hi_lo(*reinterpret_cast<const float4*>(xr + j * 4), hw, lw);
                *reinterpret_cast<u64*>(ah + j * 8) = hw;
                *reinterpret_cast<u64*>(al + j * 8) = lw;
            }
        }
        // ---- load + split B chunk: BN rows x BK k (half row per thread) ----
        {
            const int r    = tid >> 1;
            const int half = (tid & 1) * 16;
            const float* wr = &W[(size_t)(col0 + r) * DIM + kk + half];
            unsigned char* bh = smem + SM_BHI + r * (ASTRIDE * 2) + half * 2;
            unsigned char* bl = smem + SM_BLO + r * (ASTRIDE * 2) + half * 2;
#pragma unroll
            for (int j = 0; j < 4; j++) {
                u64 hw, lw;
                cvt_hi_lo(*reinterpret_cast<const float4*>(wr + j * 4), hw, lw);
                *reinterpret_cast<u64*>(bh + j * 8) = hw;
                *reinterpret_cast<u64*>(bl + j * 8) = lw;
            }
        }
        __syncthreads();

        // ---- compute: 3 splits x 2 k16-steps x (4 mi x 8 ni) mma ----
#pragma unroll
        for (int split = 0; split < 3; split++) {
            const uint16_t* As = (split == 2) ? Alo : Ahi;   // hi*hi, hi*lo, lo*hi
            const uint16_t* Bs = (split == 1) ? Blo : Bhi;
#pragma unroll
            for (int ks = 0; ks < 2; ks++) {
                const int k0 = ks * 16;
                uint32_t afr[4][4];
#pragma unroll
                for (int mi = 0; mi < 4; mi++) {
                    int rr = warpM * 64 + mi * 16 + group;
                    const uint16_t* p0 = &As[rr * ASTRIDE + k0 + tig * 2];
                    const uint16_t* p1 = p0 + 8 * ASTRIDE;
                    afr[mi][0] = *reinterpret_cast<const uint32_t*>(p0);
                    afr[mi][1] = *reinterpret_cast<const uint32_t*>(p1);
                    afr[mi][2] = *reinterpret_cast<const uint32_t*>(p0 + 8);
                    afr[mi][3] = *reinterpret_cast<const uint32_t*>(p1 + 8);
                }
                uint32_t bfr[8][2];
#pragma unroll
                for (int ni = 0; ni < 8; ni++) {
                    int cc = warpN * 64 + ni * 8 + group;
                    const uint16_t* p = &Bs[cc * ASTRIDE + k0 + tig * 2];
                    bfr[ni][0] = *reinterpret_cast<const uint32_t*>(p);
                    bfr[ni][1] = *reinterpret_cast<const uint32_t*>(p + 8);
                }
#pragma unroll
                for (int mi = 0; mi < 4; mi++)
#pragma unroll
                    for (int ni = 0; ni < 8; ni++)
                        mma16816(acc[mi][ni], afr[mi], bfr[ni]);
            }
        }
        __syncthreads();
    }

    // ---- epilogue: bias add + store (float2 per fragment row) ----
    float2 bb[8];
#pragma unroll
    for (int ni = 0; ni < 8; ni++)
        bb[ni] = *reinterpret_cast<const float2*>(&bias[col0 + warpN * 64 + ni * 8 + tig * 2]);

#pragma unroll
    for (int mi = 0; mi < 4; mi++) {
        int rg = row0 + warpM * 64 + mi * 16 + group;
#pragma unroll
        for (int ni = 0; ni < 8; ni++) {
            int cg = col0 + warpN * 64 + ni * 8 + tig * 2;
            *reinterpret_cast<float2*>(&out[(size_t)rg * DIM + cg]) =
                make_float2(acc[mi][ni][0] + bb[ni].x, acc[mi][ni][1] + bb[ni].y);
            *reinterpret_cast<float2*>(&out[(size_t)(rg + 8) * DIM + cg]) =
                make_float2(acc[mi][ni][2] + bb[ni].x, acc[mi][ni][3] + bb[ni].y);
        }
    }
}

// =====================================================================================
// Kernel 2: rfft over head_dim (32 -> 17 complex bins) for ql and kl.
// 32 tokens per CTA, thread = (token, head). Output layout [bh][f][n] (seq-contiguous).
// =====================================================================================
__global__ __launch_bounds__(256) void rfft_heads()
{
    const int which = blockIdx.y;            // 0 -> Q, 1 -> K
    const float* __restrict__ src = g_lin[which];
    float2* __restrict__ dst = g_QK[which];

    __shared__ float xs[32 * 264];           // padded rows: head h at h*33
    __shared__ float twc[32], tws[32];       // cos/sin(2*pi*k/32)

    const int tid = threadIdx.x;
    if (tid < 32) {
        float s, c;
        sincospif((float)tid * (1.0f / 16.0f), &s, &c);
        twc[tid] = c; tws[tid] = s;
    }
    const int row0 = blockIdx.x * 32;
    for (int i = tid; i < 32 * 256; i += 256) {
        int tok = i >> 8, cc = i & 255;
        xs[tok * 264 + (cc >> 5) * 33 + (cc & 31)] = src[(size_t)row0 * DIM + i];
    }
    __syncthreads();

    const int tok = tid >> 3, h = tid & 7;
    float xr[32];
#pragma unroll
    for (int d = 0; d < 32; d++) xr[d] = xs[tok * 264 + h * 33 + d];

    const int b  = row0 >> 12;
    const int n  = (row0 & (SEQ - 1)) + tok;
    const int bh = b * HEADS + h;

    for (int f = 0; f < NFREQ; f++) {
        float re = 0.0f, im = 0.0f;
#pragma unroll
        for (int d = 0; d < 32; d++) {
            int k2 = (f * d) & 31;
            re = fmaf(xr[d], twc[k2], re);
            im = fmaf(xr[d], -tws[k2], im);
        }
        dst[((size_t)bh * NFREQ + f) * SEQ + n] = make_float2(re, im);
    }
}

// =====================================================================================
// Kernel 3: per (b,h,f) column: FFT4096(Q), FFT4096(K), pointwise mult (scaled),
// inverse FFT4096 -> g_P.  Stockham radix-2 in SMEM (no bit reversal).
// =====================================================================================
__device__ __forceinline__ void fftcore(float2* x, float2* y, const float2* tw,
                                        int tid, bool inv)
{
    float2* a = x; float2* b = y;
#pragma unroll 1
    for (int ls = 0; ls < 12; ls++) {
        const int s = 1 << ls;
#pragma unroll
        for (int t = tid; t < 2048; t += 256) {
            int p = t >> ls;
            int qq = t & (s - 1);
            float2 w = tw[p << ls];
            float wy = inv ? -w.y : w.y;
            float2 u = a[t];
            float2 v = a[t + 2048];
            float2 sum = make_float2(u.x + v.x, u.y + v.y);
            float2 dif = make_float2(u.x - v.x, u.y - v.y);
            int o = qq + (p << (ls + 1));
            b[o]     = sum;
            b[o + s] = make_float2(dif.x * w.x - dif.y * wy,
                                   dif.x * wy  + dif.y * w.x);
        }
        __syncthreads();
        float2* tmp = a; a = b; b = tmp;
    }
    // 12 stages (even) -> result back in x
}

__global__ __launch_bounds__(256) void fft_conv()
{
    extern __shared__ unsigned char smraw[];
    float2* tw = reinterpret_cast<float2*>(smraw);   // 2048
    float2* bq = tw + 2048;                          // 4096 (Qhat)
    float2* ba = bq + 4096;                          // 4096 work A
    float2* bb = ba + 4096;                          // 4096 work B

    const int tid = threadIdx.x;
    const int f   = blockIdx.x;      // 0..16
    const int bh  = blockIdx.y;      // 0..63
    const size_t base = ((size_t)bh * NFREQ + f) * SEQ;

    for (int i = tid; i < 2048; i += 256) {
        float s, c;
        sincospif((float)i * (1.0f / 2048.0f), &s, &c);
        tw[i] = make_float2(c, -s);
    }
    for (int i = tid; i < 4096; i += 256) ba[i] = g_QK[0][base + i];
    __syncthreads();

    fftcore(ba, bb, tw, tid, false);                 // Qhat in ba
    for (int i = tid; i < 4096; i += 256) bq[i] = ba[i];
    __syncthreads();

    for (int i = tid; i < 4096; i += 256) ba[i] = g_QK[1][base + i];
    __syncthreads();
    fftcore(ba, bb, tw, tid, false);                 // Khat in ba

    const float scale = 1.0f / 131072.0f;            // 1/(4096*32): both inverse norms
    for (int i = tid; i < 4096; i += 256) {
        float2 a = ba[i], q2 = bq[i];
        ba[i] = make_float2((a.x * q2.x - a.y * q2.y) * scale,
                            (a.x * q2.y + a.y * q2.x) * scale);
    }
    __syncthreads();
    fftcore(ba, bb, tw, tid, true);                  // inverse -> ba

    for (int i = tid; i < 4096; i += 256) g_P[base + i] = ba[i];
}

// =====================================================================================
// Kernel 4: irfft-32 over heads + softmax(32) + value gate + residual + LayerNorm(256)
// 32 tokens per CTA; warp handles 4 tokens; lane = head_dim index d.
// =====================================================================================
__global__ __launch_bounds__(256) void epilogue(
    const float* __restrict__ vin, const float* __restrict__ gamma,
    const float* __restrict__ beta, float* __restrict__ out)
{
    __shared__ float2 Psm[HEADS * NFREQ * 32];   // [h][f][tok]
    __shared__ float c32[32], s32[32];

    const int tid = threadIdx.x;
    if (tid < 32) {
        float s, c;
        sincospif((float)tid * (1.0f / 16.0f), &s, &c);
        c32[tid] = c; s32[tid] = s;
    }
    const int row0 = blockIdx.x * 32;
    const int b = row0 >> 12, n0 = row0 & (SEQ - 1);

    for (int i = tid; i < HEADS * NFREQ * 32; i += 256) {
        int h = i / (NFREQ * 32);
        int r = i - h * (NFREQ * 32);
        int f = r >> 5, tok = r & 31;
        Psm[i] = g_P[(((size_t)(b * HEADS + h)) * NFREQ + f) * SEQ + n0 + tok];
    }
    __syncthreads();

    const int w = tid >> 5, d = tid & 31;
    const float* __restrict__ vl = g_lin[2];

    for (int it = 0; it < 4; it++) {
        const int tok = w + it * 8;
        const int row = row0 + tok;
        float gh[8];
        float s1 = 0.0f, s2 = 0.0f;
#pragma unroll
        for (int h = 0; h < 8; h++) {
            const float2* Ph = &Psm[h * NFREQ * 32 + tok];
            float acc = Ph[0].x;                       // f = 0 (real)
            float2 F16 = Ph[16 * 32];
            acc += (d & 1) ? -F16.x : F16.x;           // Nyquist (real)
#pragma unroll
            for (int f = 1; f <= 15; f++) {
                float2 F = Ph[f * 32];
                int k2 = (f * d) & 31;
                acc += 2.0f * (F.x * c32[k2] - F.y * s32[k2]);
            }
            // softmax over 32 lanes
            float m = acc;
#pragma unroll
            for (int o = 16; o; o >>= 1) m = fmaxf(m, __shfl_xor_sync(0xffffffffu, m, o));
            float e = __expf(acc - m);
            float ss = e;
#pragma unroll
            for (int o = 16; o; o >>= 1) ss += __shfl_xor_sync(0xffffffffu, ss, o);
            float p = e / ss;
            int c = h * 32 + d;
            float vv = vl[(size_t)row * DIM + c];
            float rv = vin[(size_t)row * DIM + c];
            float g = fmaf(vv, p, rv);                 // gate + residual
            gh[h] = g; s1 += g; s2 = fmaf(g, g, s2);
        }
#pragma unroll
        for (int o = 16; o; o >>= 1) {
            s1 += __shfl_xor_sync(0xffffffffu, s1, o);
            s2 += __shfl_xor_sync(0xffffffffu, s2, o);
        }
        float mean = s1 * (1.0f / 256.0f);
        float var  = s2 * (1.0f / 256.0f) - mean * mean;
        float inv  = rsqrtf(var + 1e-5f);
#pragma unroll
        for (int h = 0; h < 8; h++) {
            int c = h * 32 + d;
            out[(size_t)row * DIM + c] = (gh[h] - mean) * inv * gamma[c] + beta[c];
        }
    }
}

// =====================================================================================
extern "C" void kernel_launch(void* const* d_in, const int* in_sizes, int n_in,
                              void* d_out, int out_size)
{
    const float* q     = (const float*)d_in[0];
    const float* k     = (const float*)d_in[1];
    const float* v     = (const float*)d_in[2];
    const float* Wq    = (const float*)d_in[3];
    const float* bq    = (const float*)d_in[4];
    const float* Wk    = (const float*)d_in[5];
    const float* bk    = (const float*)d_in[6];
    const float* Wv    = (const float*)d_in[7];
    const float* bv    = (const float*)d_in[8];
    const float* gamma = (const float*)d_in[9];
    const float* beta  = (const float*)d_in[10];
    float* out = (float*)d_out;

    const int fft_smem = (2048 + 3 * 4096) * (int)sizeof(float2);  // 114688 B
    cudaFuncSetAttribute(fft_conv, cudaFuncAttributeMaxDynamicSharedMemorySize, fft_smem);
    cudaFuncSetAttribute(gemm_qkv_mma, cudaFuncAttributeMaxDynamicSharedMemorySize, SM_GEMM_TOTAL);

    gemm_qkv_mma<<<dim3(ROWS / BM, DIM / BN, 3), 256, SM_GEMM_TOTAL>>>(
        q, k, v, Wq, bq, Wk, bk, Wv, bv);
    rfft_heads<<<dim3(ROWS / 32, 2), 256>>>();
    fft_conv<<<dim3(NFREQ, BH), 256, fft_smem>>>();
    epilogue<<<ROWS / 32, 256>>>(v, gamma, beta, out);
}

// round 8
// speedup vs baseline: 1.2861x; 1.1009x over previous
#include <cuda_runtime.h>
#include <cuda_bf16.h>
#include <math_constants.h>
#include <cstdint>

// Problem constants
#define BATCH   8
#define SEQ     4096
#define DIM     256
#define HEADS   8
#define HD      32
#define NFREQ   17          // HD/2 + 1
#define ROWS    (BATCH*SEQ) // 32768
#define BH      (BATCH*HEADS) // 64

typedef unsigned long long u64;

// ---------------- scratch (static __device__ — no allocations allowed) ----------------
__device__ float  g_lin[3][(size_t)ROWS * DIM];            // ql, kl, vl
__device__ float2 g_QK[2][(size_t)BH * NFREQ * SEQ];       // Qhat, Khat
__device__ float2 g_P[(size_t)BH * NFREQ * SEQ];           // product after inverse seq-FFT
__device__ __nv_bfloat16 g_xhi[3][(size_t)ROWS * DIM];     // bf16 hi/lo split of q,k,v
__device__ __nv_bfloat16 g_xlo[3][(size_t)ROWS * DIM];
__device__ __nv_bfloat16 g_whi[3][DIM * DIM];              // and of Wq,Wk,Wv
__device__ __nv_bfloat16 g_wlo[3][DIM * DIM];

// ======================= small asm helpers ========================
__device__ __forceinline__ uint32_t smem_u32(const void* p) {
    uint32_t a;
    asm("{ .reg .u64 t; cvta.to.shared.u64 t, %1; cvt.u32.u64 %0, t; }" : "=r"(a) : "l"(p));
    return a;
}
__device__ __forceinline__ void cp16(uint32_t dst, const void* src) {
    asm volatile("cp.async.ca.shared.global [%0], [%1], 16;" :: "r"(dst), "l"(src));
}
__device__ __forceinline__ void cp_commit() { asm volatile("cp.async.commit_group;"); }
__device__ __forceinline__ void cp_wait0()  { asm volatile("cp.async.wait_group 0;"); }
__device__ __forceinline__ void ldsm4(uint32_t* r, uint32_t addr) {
    asm volatile("ldmatrix.sync.aligned.m8n8.x4.shared.b16 {%0,%1,%2,%3}, [%4];"
                 : "=r"(r[0]), "=r"(r[1]), "=r"(r[2]), "=r"(r[3]) : "r"(addr));
}
__device__ __forceinline__ void mma16816(float* c, const uint32_t* a, const uint32_t* b) {
    asm volatile(
        "mma.sync.aligned.m16n8k16.row.col.f32.bf16.bf16.f32 "
        "{%0,%1,%2,%3}, {%4,%5,%6,%7}, {%8,%9}, {%0,%1,%2,%3};"
        : "+f"(c[0]), "+f"(c[1]), "+f"(c[2]), "+f"(c[3])
        : "r"(a[0]), "r"(a[1]), "r"(a[2]), "r"(a[3]), "r"(b[0]), "r"(b[1]));
}
__device__ __forceinline__ void cvt_hi_lo(float4 xv, u64& hw, u64& lw) {
    __nv_bfloat16 h0 = __float2bfloat16_rn(xv.x);
    __nv_bfloat16 h1 = __float2bfloat16_rn(xv.y);
    __nv_bfloat16 h2 = __float2bfloat16_rn(xv.z);
    __nv_bfloat16 h3 = __float2bfloat16_rn(xv.w);
    __nv_bfloat16 l0 = __float2bfloat16_rn(xv.x - __bfloat162float(h0));
    __nv_bfloat16 l1 = __float2bfloat16_rn(xv.y - __bfloat162float(h1));
    __nv_bfloat16 l2 = __float2bfloat16_rn(xv.z - __bfloat162float(h2));
    __nv_bfloat16 l3 = __float2bfloat16_rn(xv.w - __bfloat162float(h3));
    hw = (u64)__bfloat16_as_ushort(h0) | ((u64)__bfloat16_as_ushort(h1) << 16)
       | ((u64)__bfloat16_as_ushort(h2) << 32) | ((u64)__bfloat16_as_ushort(h3) << 48);
    lw = (u64)__bfloat16_as_ushort(l0) | ((u64)__bfloat16_as_ushort(l1) << 16)
       | ((u64)__bfloat16_as_ushort(l2) << 32) | ((u64)__bfloat16_as_ushort(l3) << 48);
}

// =====================================================================================
// Kernel 0: fp32 -> bf16 hi/lo split for X (q,k,v) and W (Wq,Wk,Wv). Pure streaming.
// =====================================================================================
#define NX4 (3 * ROWS * DIM / 4)
#define NW4 (3 * DIM * DIM / 4)
__global__ __launch_bounds__(256) void convert_bf16(
    const float* __restrict__ q, const float* __restrict__ k, const float* __restrict__ v,
    const float* __restrict__ Wq, const float* __restrict__ Wk, const float* __restrict__ Wv)
{
    const int idx = blockIdx.x * 256 + threadIdx.x;
    u64 hw, lw;
    if (idx < NX4) {
        const int per = ROWS * DIM / 4;
        const int z = idx / per, off = idx - z * per;
        const float* src = (z == 0) ? q : (z == 1) ? k : v;
        cvt_hi_lo(reinterpret_cast<const float4*>(src)[off], hw, lw);
        reinterpret_cast<u64*>(g_xhi[z])[off] = hw;
        reinterpret_cast<u64*>(g_xlo[z])[off] = lw;
    } else if (idx < NX4 + NW4) {
        const int per = DIM * DIM / 4;
        const int iw = idx - NX4;
        const int z = iw / per, off = iw - z * per;
        const float* src = (z == 0) ? Wq : (z == 1) ? Wk : Wv;
        cvt_hi_lo(reinterpret_cast<const float4*>(src)[off], hw, lw);
        reinterpret_cast<u64*>(g_whi[z])[off] = hw;
        reinterpret_cast<u64*>(g_wlo[z])[off] = lw;
    }
}

// =====================================================================================
// Kernel 1: QKV GEMM on mma.sync, operands pre-split bf16, cp.async double buffer,
// ldmatrix fragments. CTA: M=256 x N=128, K chunks of 32. 8 warps = 4(M) x 2(N).
// 3 products per chunk: hi*hi + hi*lo + lo*hi, fp32 accumulate.
// =====================================================================================
#define BM 256
#define BN 128
#define BK 32
#define RB 80                 // bytes per SMEM row (40 bf16: 32 data + pad; 16B-aligned)
// per-buffer byte offsets
#define OF_AHI 0
#define OF_ALO (BM * RB)                  // 20480
#define OF_BHI (2 * BM * RB)              // 40960
#define OF_BLO (2 * BM * RB + BN * RB)    // 51200
#define BUF_SZ (2 * BM * RB + 2 * BN * RB) // 61440
#define SM_GEMM_TOTAL (2 * BUF_SZ)         // 122880

__device__ __forceinline__ void gemm_load_chunk(
    uint32_t buf, int tid, int kk, int row0, int col0,
    const __nv_bfloat16* Xhi, const __nv_bfloat16* Xlo,
    const __nv_bfloat16* Whi, const __nv_bfloat16* Wlo)
{
#pragma unroll
    for (int i = 0; i < 4; i++) {                 // A: 256 rows x 2 (hi/lo) x 64B
        int idx = tid + 256 * i;
        int row = idx >> 2, j = idx & 3;
        size_t g = (size_t)(row0 + row) * DIM + kk + j * 8;
        uint32_t d = buf + row * RB + j * 16;
        cp16(d + OF_AHI, Xhi + g);
        cp16(d + OF_ALO, Xlo + g);
    }
#pragma unroll
    for (int i = 0; i < 2; i++) {                 // B: 128 rows x 2 x 64B
        int idx = tid + 256 * i;
        int row = idx >> 2, j = idx & 3;
        size_t g = (size_t)(col0 + row) * DIM + kk + j * 8;
        uint32_t d = buf + row * RB + j * 16;
        cp16(d + OF_BHI, Whi + g);
        cp16(d + OF_BLO, Wlo + g);
    }
}

__global__ __launch_bounds__(256) void gemm_qkv_mma(
    const float* __restrict__ bq, const float* __restrict__ bk, const float* __restrict__ bv)
{
    extern __shared__ unsigned char smem[];
    const uint32_t sbase = smem_u32(smem);

    const int z = blockIdx.z;
    const __nv_bfloat16* Xhi = g_xhi[z];
    const __nv_bfloat16* Xlo = g_xlo[z];
    const __nv_bfloat16* Whi = g_whi[z];
    const __nv_bfloat16* Wlo = g_wlo[z];
    const float* bias = (z == 0) ? bq : (z == 1) ? bk : bv;
    float* out = g_lin[z];

    const int tid   = threadIdx.x;
    const int wid   = tid >> 5;
    const int lane  = tid & 31;
    const int group = lane >> 2;
    const int tig   = lane & 3;
    const int warpM = wid >> 1;       // 0..3 (x64)
    const int warpN = wid & 1;        // 0..1 (x64)
    const int row0  = blockIdx.x * BM;
    const int col0  = blockIdx.y * BN;

    // per-lane ldmatrix addressing
    const int tile = lane >> 3, ti = lane & 7;
    const uint32_t rowA = (uint32_t)(warpM * 64 + ((tile & 1) << 3) + ti) * RB;
    const uint32_t rowB = (uint32_t)(warpN * 64 + ((tile & 1) << 3) + ti) * RB;
    const uint32_t colT = (uint32_t)((tile >> 1) << 3) * 2;   // bytes

    float acc[4][8][4];
#pragma unroll
    for (int mi = 0; mi < 4; mi++)
#pragma unroll
        for (int ni = 0; ni < 8; ni++)
#pragma unroll
            for (int r = 0; r < 4; r++) acc[mi][ni][r] = 0.0f;

    gemm_load_chunk(sbase, tid, 0, row0, col0, Xhi, Xlo, Whi, Wlo);
    cp_commit();

#pragma unroll 1
    for (int c = 0; c < DIM / BK; c++) {
        cp_wait0();
        __syncthreads();
        if (c + 1 < DIM / BK) {
            gemm_load_chunk(sbase + ((c + 1) & 1) * BUF_SZ, tid, (c + 1) * BK,
                            row0, col0, Xhi, Xlo, Whi, Wlo);
            cp_commit();
        }
        const uint32_t buf = sbase + (c & 1) * BUF_SZ;

#pragma unroll
        for (int ks = 0; ks < 2; ks++) {
            const uint32_t kb = (uint32_t)(ks * 32) + colT;
            uint32_t ahi[4][4], alo[4][4], bhi[4][4], blo[4][4];
#pragma unroll
            for (int mi = 0; mi < 4; mi++) {
                ldsm4(ahi[mi], buf + OF_AHI + rowA + mi * (16 * RB) + kb);
                ldsm4(alo[mi], buf + OF_ALO + rowA + mi * (16 * RB) + kb);
            }
#pragma unroll
            for (int p = 0; p < 4; p++) {
                ldsm4(bhi[p], buf + OF_BHI + rowB + p * (16 * RB) + kb);
                ldsm4(blo[p], buf + OF_BLO + rowB + p * (16 * RB) + kb);
            }
#pragma unroll
            for (int mi = 0; mi < 4; mi++) {
#pragma unroll
                for (int ni = 0; ni < 8; ni++) {
                    const int p = ni >> 1, s = ni & 1;
                    uint32_t bh[2] = {bhi[p][s], bhi[p][2 + s]};
                    uint32_t bl[2] = {blo[p][s], blo[p][2 + s]};
                    mma16816(acc[mi][ni], ahi[mi], bh);   // hi*hi
                    mma16816(acc[mi][ni], ahi[mi], bl);   // hi*lo
                    mma16816(acc[mi][ni], alo[mi], bh);   // lo*hi
                }
            }
        }
        __syncthreads();
    }

    // ---- epilogue: bias add + store ----
    float2 bb[8];
#pragma unroll
    for (int ni = 0; ni < 8; ni++)
        bb[ni] = *reinterpret_cast<const float2*>(&bias[col0 + warpN * 64 + ni * 8 + tig * 2]);

#pragma unroll
    for (int mi = 0; mi < 4; mi++) {
        int rg = row0 + warpM * 64 + mi * 16 + group;
#pragma unroll
        for (int ni = 0; ni < 8; ni++) {
            int cg = col0 + warpN * 64 + ni * 8 + tig * 2;
            *reinterpret_cast<float2*>(&out[(size_t)rg * DIM + cg]) =
                make_float2(acc[mi][ni][0] + bb[ni].x, acc[mi][ni][1] + bb[ni].y);
            *reinterpret_cast<float2*>(&out[(size_t)(rg + 8) * DIM + cg]) =
                make_float2(acc[mi][ni][2] + bb[ni].x, acc[mi][ni][3] + bb[ni].y);
        }
    }
}

// =====================================================================================
// Kernel 2: rfft over head_dim (32 -> 17 complex bins) for ql and kl.
// =====================================================================================
__global__ __launch_bounds__(256) void rfft_heads()
{
    const int which = blockIdx.y;            // 0 -> Q, 1 -> K
    const float* __restrict__ src = g_lin[which];
    float2* __restrict__ dst = g_QK[which];

    __shared__ float xs[32 * 264];           // padded rows: head h at h*33
    __shared__ float twc[32], tws[32];

    const int tid = threadIdx.x;
    if (tid < 32) {
        float s, c;
        sincospif((float)tid * (1.0f / 16.0f), &s, &c);
        twc[tid] = c; tws[tid] = s;
    }
    const int row0 = blockIdx.x * 32;
    for (int i = tid; i < 32 * 256; i += 256) {
        int tok = i >> 8, cc = i & 255;
        xs[tok * 264 + (cc >> 5) * 33 + (cc & 31)] = src[(size_t)row0 * DIM + i];
    }
    __syncthreads();

    const int tok = tid >> 3, h = tid & 7;
    float xr[32];
#pragma unroll
    for (int d = 0; d < 32; d++) xr[d] = xs[tok * 264 + h * 33 + d];

    const int b  = row0 >> 12;
    const int n  = (row0 & (SEQ - 1)) + tok;
    const int bh = b * HEADS + h;

    for (int f = 0; f < NFREQ; f++) {
        float re = 0.0f, im = 0.0f;
#pragma unroll
        for (int d = 0; d < 32; d++) {
            int k2 = (f * d) & 31;
            re = fmaf(xr[d], twc[k2], re);
            im = fmaf(xr[d], -tws[k2], im);
        }
        dst[((size_t)bh * NFREQ + f) * SEQ + n] = make_float2(re, im);
    }
}

// =====================================================================================
// Kernel 3: per (b,h,f) column: FFT4096(Q), FFT4096(K), pointwise mult (scaled),
// inverse FFT4096 -> g_P.  Stockham radix-2 in SMEM.
// =====================================================================================
__device__ __forceinline__ void fftcore(float2* x, float2* y, const float2* tw,
                                        int tid, bool inv)
{
    float2* a = x; float2* b = y;
#pragma unroll 1
    for (int ls = 0; ls < 12; ls++) {
        const int s = 1 << ls;
#pragma unroll
        for (int t = tid; t < 2048; t += 256) {
            int p = t >> ls;
            int qq = t & (s - 1);
            float2 w = tw[p << ls];
            float wy = inv ? -w.y : w.y;
            float2 u = a[t];
            float2 v = a[t + 2048];
            float2 sum = make_float2(u.x + v.x, u.y + v.y);
            float2 dif = make_float2(u.x - v.x, u.y - v.y);
            int o = qq + (p << (ls + 1));
            b[o]     = sum;
            b[o + s] = make_float2(dif.x * w.x - dif.y * wy,
                                   dif.x * wy  + dif.y * w.x);
        }
        __syncthreads();
        float2* tmp = a; a = b; b = tmp;
    }
}

__global__ __launch_bounds__(256) void fft_conv()
{
    extern __shared__ unsigned char smraw[];
    float2* tw = reinterpret_cast<float2*>(smraw);   // 2048
    float2* bq = tw + 2048;                          // 4096 (Qhat)
    float2* ba = bq + 4096;                          // 4096 work A
    float2* bb = ba + 4096;                          // 4096 work B

    const int tid = threadIdx.x;
    const int f   = blockIdx.x;      // 0..16
    const int bh  = blockIdx.y;      // 0..63
    const size_t base = ((size_t)bh * NFREQ + f) * SEQ;

    for (int i = tid; i < 2048; i += 256) {
        float s, c;
        sincospif((float)i * (1.0f / 2048.0f), &s, &c);
        tw[i] = make_float2(c, -s);
    }
    for (int i = tid; i < 4096; i += 256) ba[i] = g_QK[0][base + i];
    __syncthreads();

    fftcore(ba, bb, tw, tid, false);                 // Qhat in ba
    for (int i = tid; i < 4096; i += 256) bq[i] = ba[i];
    __syncthreads();

    for (int i = tid; i < 4096; i += 256) ba[i] = g_QK[1][base + i];
    __syncthreads();
    fftcore(ba, bb, tw, tid, false);                 // Khat in ba

    const float scale = 1.0f / 131072.0f;            // 1/(4096*32)
    for (int i = tid; i < 4096; i += 256) {
        float2 a = ba[i], q2 = bq[i];
        ba[i] = make_float2((a.x * q2.x - a.y * q2.y) * scale,
                            (a.x * q2.y + a.y * q2.x) * scale);
    }
    __syncthreads();
    fftcore(ba, bb, tw, tid, true);                  // inverse -> ba

    for (int i = tid; i < 4096; i += 256) g_P[base + i] = ba[i];
}

// =====================================================================================
// Kernel 4: irfft-32 over heads + softmax(32) + value gate + residual + LayerNorm(256)
// =====================================================================================
__global__ __launch_bounds__(256) void epilogue(
    const float* __restrict__ vin, const float* __restrict__ gamma,
    const float* __restrict__ beta, float* __restrict__ out)
{
    __shared__ float2 Psm[HEADS * NFREQ * 32];   // [h][f][tok]
    __shared__ float c32[32], s32[32];

    const int tid = threadIdx.x;
    if (tid < 32) {
        float s, c;
        sincospif((float)tid * (1.0f / 16.0f), &s, &c);
        c32[tid] = c; s32[tid] = s;
    }
    const int row0 = blockIdx.x * 32;
    const int b = row0 >> 12, n0 = row0 & (SEQ - 1);

    for (int i = tid; i < HEADS * NFREQ * 32; i += 256) {
        int h = i / (NFREQ * 32);
        int r = i - h * (NFREQ * 32);
        int f = r >> 5, tok = r & 31;
        Psm[i] = g_P[(((size_t)(b * HEADS + h)) * NFREQ + f) * SEQ + n0 + tok];
    }
    __syncthreads();

    const int w = tid >> 5, d = tid & 31;
    const float* __restrict__ vl = g_lin[2];

    for (int it = 0; it < 4; it++) {
        const int tok = w + it * 8;
        const int row = row0 + tok;
        float gh[8];
        float s1 = 0.0f, s2 = 0.0f;
#pragma unroll
        for (int h = 0; h < 8; h++) {
            const float2* Ph = &Psm[h * NFREQ * 32 + tok];
            float acc = Ph[0].x;                       // f = 0 (real)
            float2 F16 = Ph[16 * 32];
            acc += (d & 1) ? -F16.x : F16.x;           // Nyquist (real)
#pragma unroll
            for (int f = 1; f <= 15; f++) {
                float2 F = Ph[f * 32];
                int k2 = (f * d) & 31;
                acc += 2.0f * (F.x * c32[k2] - F.y * s32[k2]);
            }
            float m = acc;
#pragma unroll
            for (int o = 16; o; o >>= 1) m = fmaxf(m, __shfl_xor_sync(0xffffffffu, m, o));
            float e = __expf(acc - m);
            float ss = e;
#pragma unroll
            for (int o = 16; o; o >>= 1) ss += __shfl_xor_sync(0xffffffffu, ss, o);
            float p = e / ss;
            int c = h * 32 + d;
            float vv = vl[(size_t)row * DIM + c];
            float rv = vin[(size_t)row * DIM + c];
            float g = fmaf(vv, p, rv);                 // gate + residual
            gh[h] = g; s1 += g; s2 = fmaf(g, g, s2);
        }
#pragma unroll
        for (int o = 16; o; o >>= 1) {
            s1 += __shfl_xor_sync(0xffffffffu, s1, o);
            s2 += __shfl_xor_sync(0xffffffffu, s2, o);
        }
        float mean = s1 * (1.0f / 256.0f);
        float var  = s2 * (1.0f / 256.0f) - mean * mean;
        float inv  = rsqrtf(var + 1e-5f);
#pragma unroll
        for (int h = 0; h < 8; h++) {
            int c = h * 32 + d;
            out[(size_t)row * DIM + c] = (gh[h] - mean) * inv * gamma[c] + beta[c];
        }
    }
}

// =====================================================================================
extern "C" void kernel_launch(void* const* d_in, const int* in_sizes, int n_in,
                              void* d_out, int out_size)
{
    const float* q     = (const float*)d_in[0];
    const float* k     = (const float*)d_in[1];
    const float* v     = (const float*)d_in[2];
    const float* Wq    = (const float*)d_in[3];
    const float* bq    = (const float*)d_in[4];
    const float* Wk    = (const float*)d_in[5];
    const float* bk    = (const float*)d_in[6];
    const float* Wv    = (const float*)d_in[7];
    const float* bv    = (const float*)d_in[8];
    const float* gamma = (const float*)d_in[9];
    const float* beta  = (const float*)d_in[10];
    float* out = (float*)d_out;

    const int fft_smem = (2048 + 3 * 4096) * (int)sizeof(float2);  // 114688 B
    cudaFuncSetAttribute(fft_conv, cudaFuncAttributeMaxDynamicSharedMemorySize, fft_smem);
    cudaFuncSetAttribute(gemm_qkv_mma, cudaFuncAttributeMaxDynamicSharedMemorySize, SM_GEMM_TOTAL);

    convert_bf16<<<(NX4 + NW4 + 255) / 256, 256>>>(q, k, v, Wq, Wk, Wv);
    gemm_qkv_mma<<<dim3(ROWS / BM, DIM / BN, 3), 256, SM_GEMM_TOTAL>>>(bq, bk, bv);
    rfft_heads<<<dim3(ROWS / 32, 2), 256>>>();
    fft_conv<<<dim3(NFREQ, BH), 256, fft_smem>>>();
    epilogue<<<ROWS / 32, 256>>>(v, gamma, beta, out);
}

// round 9
// speedup vs baseline: 1.5104x; 1.1744x over previous
#include <cuda_runtime.h>
#include <cuda_bf16.h>
#include <math_constants.h>
#include <cstdint>

// Problem constants
#define BATCH   8
#define SEQ     4096
#define DIM     256
#define HEADS   8
#define HD      32
#define NFREQ   17          // HD/2 + 1
#define ROWS    (BATCH*SEQ) // 32768
#define BH      (BATCH*HEADS) // 64

typedef unsigned long long u64;

// ---------------- scratch (static __device__ — no allocations allowed) ----------------
__device__ float  g_lin[3][(size_t)ROWS * DIM];            // ql, kl, vl
__device__ float2 g_QK[2][(size_t)BH * NFREQ * SEQ];       // Qhat, Khat
__device__ float2 g_P[(size_t)BH * NFREQ * SEQ];           // product after inverse seq-FFT
__device__ __nv_bfloat16 g_xhi[3][(size_t)ROWS * DIM];     // bf16 hi/lo split of q,k,v
__device__ __nv_bfloat16 g_xlo[3][(size_t)ROWS * DIM];
__device__ __nv_bfloat16 g_whi[3][DIM * DIM];              // and of Wq,Wk,Wv
__device__ __nv_bfloat16 g_wlo[3][DIM * DIM];

// ======================= small asm helpers ========================
__device__ __forceinline__ uint32_t smem_u32(const void* p) {
    uint32_t a;
    asm("{ .reg .u64 t; cvta.to.shared.u64 t, %1; cvt.u32.u64 %0, t; }" : "=r"(a) : "l"(p));
    return a;
}
__device__ __forceinline__ void cp16(uint32_t dst, const void* src) {
    asm volatile("cp.async.ca.shared.global [%0], [%1], 16;" :: "r"(dst), "l"(src));
}
__device__ __forceinline__ void cp_commit() { asm volatile("cp.async.commit_group;"); }
__device__ __forceinline__ void cp_wait0()  { asm volatile("cp.async.wait_group 0;"); }
__device__ __forceinline__ void ldsm4(uint32_t* r, uint32_t addr) {
    asm volatile("ldmatrix.sync.aligned.m8n8.x4.shared.b16 {%0,%1,%2,%3}, [%4];"
                 : "=r"(r[0]), "=r"(r[1]), "=r"(r[2]), "=r"(r[3]) : "r"(addr));
}
__device__ __forceinline__ void mma16816(float* c, const uint32_t* a, const uint32_t* b) {
    asm volatile(
        "mma.sync.aligned.m16n8k16.row.col.f32.bf16.bf16.f32 "
        "{%0,%1,%2,%3}, {%4,%5,%6,%7}, {%8,%9}, {%0,%1,%2,%3};"
        : "+f"(c[0]), "+f"(c[1]), "+f"(c[2]), "+f"(c[3])
        : "r"(a[0]), "r"(a[1]), "r"(a[2]), "r"(a[3]), "r"(b[0]), "r"(b[1]));
}
__device__ __forceinline__ void cvt_hi_lo(float4 xv, u64& hw, u64& lw) {
    __nv_bfloat16 h0 = __float2bfloat16_rn(xv.x);
    __nv_bfloat16 h1 = __float2bfloat16_rn(xv.y);
    __nv_bfloat16 h2 = __float2bfloat16_rn(xv.z);
    __nv_bfloat16 h3 = __float2bfloat16_rn(xv.w);
    __nv_bfloat16 l0 = __float2bfloat16_rn(xv.x - __bfloat162float(h0));
    __nv_bfloat16 l1 = __float2bfloat16_rn(xv.y - __bfloat162float(h1));
    __nv_bfloat16 l2 = __float2bfloat16_rn(xv.z - __bfloat162float(h2));
    __nv_bfloat16 l3 = __float2bfloat16_rn(xv.w - __bfloat162float(h3));
    hw = (u64)__bfloat16_as_ushort(h0) | ((u64)__bfloat16_as_ushort(h1) << 16)
       | ((u64)__bfloat16_as_ushort(h2) << 32) | ((u64)__bfloat16_as_ushort(h3) << 48);
    lw = (u64)__bfloat16_as_ushort(l0) | ((u64)__bfloat16_as_ushort(l1) << 16)
       | ((u64)__bfloat16_as_ushort(l2) << 32) | ((u64)__bfloat16_as_ushort(l3) << 48);
}

// =====================================================================================
// Kernel 0: fp32 -> bf16 hi/lo split for X (q,k,v) and W (Wq,Wk,Wv). Pure streaming.
// =====================================================================================
#define NX4 (3 * ROWS * DIM / 4)
#define NW4 (3 * DIM * DIM / 4)
__global__ __launch_bounds__(256) void convert_bf16(
    const float* __restrict__ q, const float* __restrict__ k, const float* __restrict__ v,
    const float* __restrict__ Wq, const float* __restrict__ Wk, const float* __restrict__ Wv)
{
    const int idx = blockIdx.x * 256 + threadIdx.x;
    u64 hw, lw;
    if (idx < NX4) {
        const int per = ROWS * DIM / 4;
        const int z = idx / per, off = idx - z * per;
        const float* src = (z == 0) ? q : (z == 1) ? k : v;
        cvt_hi_lo(reinterpret_cast<const float4*>(src)[off], hw, lw);
        reinterpret_cast<u64*>(g_xhi[z])[off] = hw;
        reinterpret_cast<u64*>(g_xlo[z])[off] = lw;
    } else if (idx < NX4 + NW4) {
        const int per = DIM * DIM / 4;
        const int iw = idx - NX4;
        const int z = iw / per, off = iw - z * per;
        const float* src = (z == 0) ? Wq : (z == 1) ? Wk : Wv;
        cvt_hi_lo(reinterpret_cast<const float4*>(src)[off], hw, lw);
        reinterpret_cast<u64*>(g_whi[z])[off] = hw;
        reinterpret_cast<u64*>(g_wlo[z])[off] = lw;
    }
}

// =====================================================================================
// Kernel 1: QKV GEMM on mma.sync, operands pre-split bf16, cp.async double buffer,
// ldmatrix fragments. CTA: M=256 x N=128, K chunks of 32. 8 warps = 4(M) x 2(N).
// =====================================================================================
#define BM 256
#define BN 128
#define BK 32
#define RB 80                 // bytes per SMEM row (40 bf16)
#define OF_AHI 0
#define OF_ALO (BM * RB)
#define OF_BHI (2 * BM * RB)
#define OF_BLO (2 * BM * RB + BN * RB)
#define BUF_SZ (2 * BM * RB + 2 * BN * RB)
#define SM_GEMM_TOTAL (2 * BUF_SZ)         // 122880

__device__ __forceinline__ void gemm_load_chunk(
    uint32_t buf, int tid, int kk, int row0, int col0,
    const __nv_bfloat16* Xhi, const __nv_bfloat16* Xlo,
    const __nv_bfloat16* Whi, const __nv_bfloat16* Wlo)
{
#pragma unroll
    for (int i = 0; i < 4; i++) {
        int idx = tid + 256 * i;
        int row = idx >> 2, j = idx & 3;
        size_t g = (size_t)(row0 + row) * DIM + kk + j * 8;
        uint32_t d = buf + row * RB + j * 16;
        cp16(d + OF_AHI, Xhi + g);
        cp16(d + OF_ALO, Xlo + g);
    }
#pragma unroll
    for (int i = 0; i < 2; i++) {
        int idx = tid + 256 * i;
        int row = idx >> 2, j = idx & 3;
        size_t g = (size_t)(col0 + row) * DIM + kk + j * 8;
        uint32_t d = buf + row * RB + j * 16;
        cp16(d + OF_BHI, Whi + g);
        cp16(d + OF_BLO, Wlo + g);
    }
}

__global__ __launch_bounds__(256) void gemm_qkv_mma(
    const float* __restrict__ bq, const float* __restrict__ bk, const float* __restrict__ bv)
{
    extern __shared__ unsigned char smem[];
    const uint32_t sbase = smem_u32(smem);

    const int z = blockIdx.z;
    const __nv_bfloat16* Xhi = g_xhi[z];
    const __nv_bfloat16* Xlo = g_xlo[z];
    const __nv_bfloat16* Whi = g_whi[z];
    const __nv_bfloat16* Wlo = g_wlo[z];
    const float* bias = (z == 0) ? bq : (z == 1) ? bk : bv;
    float* out = g_lin[z];

    const int tid   = threadIdx.x;
    const int wid   = tid >> 5;
    const int lane  = tid & 31;
    const int group = lane >> 2;
    const int tig   = lane & 3;
    const int warpM = wid >> 1;
    const int warpN = wid & 1;
    const int row0  = blockIdx.x * BM;
    const int col0  = blockIdx.y * BN;

    const int tile = lane >> 3, ti = lane & 7;
    const uint32_t rowA = (uint32_t)(warpM * 64 + ((tile & 1) << 3) + ti) * RB;
    const uint32_t rowB = (uint32_t)(warpN * 64 + ((tile & 1) << 3) + ti) * RB;
    const uint32_t colT = (uint32_t)((tile >> 1) << 3) * 2;

    float acc[4][8][4];
#pragma unroll
    for (int mi = 0; mi < 4; mi++)
#pragma unroll
        for (int ni = 0; ni < 8; ni++)
#pragma unroll
            for (int r = 0; r < 4; r++) acc[mi][ni][r] = 0.0f;

    gemm_load_chunk(sbase, tid, 0, row0, col0, Xhi, Xlo, Whi, Wlo);
    cp_commit();

#pragma unroll 1
    for (int c = 0; c < DIM / BK; c++) {
        cp_wait0();
        __syncthreads();
        if (c + 1 < DIM / BK) {
            gemm_load_chunk(sbase + ((c + 1) & 1) * BUF_SZ, tid, (c + 1) * BK,
                            row0, col0, Xhi, Xlo, Whi, Wlo);
            cp_commit();
        }
        const uint32_t buf = sbase + (c & 1) * BUF_SZ;

#pragma unroll
        for (int ks = 0; ks < 2; ks++) {
            const uint32_t kb = (uint32_t)(ks * 32) + colT;
            uint32_t ahi[4][4], alo[4][4], bhi[4][4], blo[4][4];
#pragma unroll
            for (int mi = 0; mi < 4; mi++) {
                ldsm4(ahi[mi], buf + OF_AHI + rowA + mi * (16 * RB) + kb);
                ldsm4(alo[mi], buf + OF_ALO + rowA + mi * (16 * RB) + kb);
            }
#pragma unroll
            for (int p = 0; p < 4; p++) {
                ldsm4(bhi[p], buf + OF_BHI + rowB + p * (16 * RB) + kb);
                ldsm4(blo[p], buf + OF_BLO + rowB + p * (16 * RB) + kb);
            }
#pragma unroll
            for (int mi = 0; mi < 4; mi++) {
#pragma unroll
                for (int ni = 0; ni < 8; ni++) {
                    const int p = ni >> 1, s = ni & 1;
                    uint32_t bh[2] = {bhi[p][s], bhi[p][2 + s]};
                    uint32_t bl[2] = {blo[p][s], blo[p][2 + s]};
                    mma16816(acc[mi][ni], ahi[mi], bh);
                    mma16816(acc[mi][ni], ahi[mi], bl);
                    mma16816(acc[mi][ni], alo[mi], bh);
                }
            }
        }
        __syncthreads();
    }

    float2 bb[8];
#pragma unroll
    for (int ni = 0; ni < 8; ni++)
        bb[ni] = *reinterpret_cast<const float2*>(&bias[col0 + warpN * 64 + ni * 8 + tig * 2]);

#pragma unroll
    for (int mi = 0; mi < 4; mi++) {
        int rg = row0 + warpM * 64 + mi * 16 + group;
#pragma unroll
        for (int ni = 0; ni < 8; ni++) {
            int cg = col0 + warpN * 64 + ni * 8 + tig * 2;
            *reinterpret_cast<float2*>(&out[(size_t)rg * DIM + cg]) =
                make_float2(acc[mi][ni][0] + bb[ni].x, acc[mi][ni][1] + bb[ni].y);
            *reinterpret_cast<float2*>(&out[(size_t)(rg + 8) * DIM + cg]) =
                make_float2(acc[mi][ni][2] + bb[ni].x, acc[mi][ni][3] + bb[ni].y);
        }
    }
}

// =====================================================================================
// Kernel 2: rfft over head_dim (32 -> 17 complex bins) for ql and kl.
// =====================================================================================
__global__ __launch_bounds__(256) void rfft_heads()
{
    const int which = blockIdx.y;            // 0 -> Q, 1 -> K
    const float* __restrict__ src = g_lin[which];
    float2* __restrict__ dst = g_QK[which];

    __shared__ float xs[32 * 264];
    __shared__ float twc[32], tws[32];

    const int tid = threadIdx.x;
    if (tid < 32) {
        float s, c;
        sincospif((float)tid * (1.0f / 16.0f), &s, &c);
        twc[tid] = c; tws[tid] = s;
    }
    const int row0 = blockIdx.x * 32;
    for (int i = tid; i < 32 * 256; i += 256) {
        int tok = i >> 8, cc = i & 255;
        xs[tok * 264 + (cc >> 5) * 33 + (cc & 31)] = src[(size_t)row0 * DIM + i];
    }
    __syncthreads();

    const int tok = tid >> 3, h = tid & 7;
    float xr[32];
#pragma unroll
    for (int d = 0; d < 32; d++) xr[d] = xs[tok * 264 + h * 33 + d];

    const int b  = row0 >> 12;
    const int n  = (row0 & (SEQ - 1)) + tok;
    const int bh = b * HEADS + h;

    for (int f = 0; f < NFREQ; f++) {
        float re = 0.0f, im = 0.0f;
#pragma unroll
        for (int d = 0; d < 32; d++) {
            int k2 = (f * d) & 31;
            re = fmaf(xr[d], twc[k2], re);
            im = fmaf(xr[d], -tws[k2], im);
        }
        dst[((size_t)bh * NFREQ + f) * SEQ + n] = make_float2(re, im);
    }
}

// =====================================================================================
// Kernel 3: per (b,h,f) column: FFT4096(Q), FFT4096(K), pointwise mult (scaled),
// inverse FFT4096 -> g_P.  Radix-4 Stockham (6 fused stages), Qhat in registers.
// SMEM: tw(16KB) + 2 work buffers(64KB) = 80KB -> 2 CTAs/SM.
// =====================================================================================
__device__ __forceinline__ void fft6(float2* __restrict__ xin, float2* __restrict__ yin,
                                     const float2* __restrict__ tw, int tid, bool inv)
{
    float2* x = xin; float2* y = yin;
#pragma unroll 1
    for (int st = 0; st < 6; st++) {
        const int S = 1 << (2 * st);          // 1,4,16,64,256,1024
#pragma unroll
        for (int it = 0; it < 4; it++) {
            const int j  = tid + (it << 8);   // 0..1023
            const int qq = j & (S - 1);
            const int pS = j - qq;            // p*S
            float2 x0 = x[j], x1 = x[j + 1024], x2 = x[j + 2048], x3 = x[j + 3072];
            float2 w1 = tw[pS];
            float2 w2 = tw[2 * pS];
            const float w1y = inv ? -w1.y : w1.y;
            const float w2y = inv ? -w2.y : w2.y;
            float e0x = x0.x + x2.x, e0y = x0.y + x2.y;
            float e1x = x1.x + x3.x, e1y = x1.y + x3.y;
            float d0x = x0.x - x2.x, d0y = x0.y - x2.y;
            float d1x = x1.x - x3.x, d1y = x1.y - x3.y;
            // t = (inv ? +i : -i) * d1
            float tx = inv ? -d1y :  d1y;
            float ty = inv ?  d1x : -d1x;
            float o0x = d0x * w1.x - d0y * w1y, o0y = d0x * w1y + d0y * w1.x;
            float o1x = tx  * w1.x - ty  * w1y, o1y = tx  * w1y + ty  * w1.x;
            const int o = 4 * pS + qq;
            y[o] = make_float2(e0x + e1x, e0y + e1y);
            y[o + S] = make_float2(o0x + o1x, o0y + o1y);
            float f2x = e0x - e1x, f2y = e0y - e1y;
            y[o + 2 * S] = make_float2(f2x * w2.x - f2y * w2y, f2x * w2y + f2y * w2.x);
            float f3x = o0x - o1x, f3y = o0y - o1y;
            y[o + 3 * S] = make_float2(f3x * w2.x - f3y * w2y, f3x * w2y + f3y * w2.x);
        }
        __syncthreads();
        float2* tmp = x; x = y; y = tmp;
    }
    // 6 swaps -> result back in xin
}

__global__ __launch_bounds__(256) void fft_conv()
{
    extern __shared__ unsigned char smraw[];
    float2* tw = reinterpret_cast<float2*>(smraw);   // 2048
    float2* ba = tw + 2048;                          // 4096 work A
    float2* bb = ba + 4096;                          // 4096 work B

    const int tid = threadIdx.x;
    const int f   = blockIdx.x;      // 0..16
    const int bh  = blockIdx.y;      // 0..63
    const size_t base = ((size_t)bh * NFREQ + f) * SEQ;

    for (int i = tid; i < 2048; i += 256) {
        float s, c;
        sincospif((float)i * (1.0f / 2048.0f), &s, &c);
        tw[i] = make_float2(c, -s);
    }
#pragma unroll
    for (int r = 0; r < 16; r++) ba[tid + 256 * r] = g_QK[0][base + tid + 256 * r];
    __syncthreads();

    fft6(ba, bb, tw, tid, false);                    // Qhat in ba

    // stash Qhat in registers (each thread owns indices tid + 256*r -> conflict-free)
    float2 qreg[16];
#pragma unroll
    for (int r = 0; r < 16; r++) qreg[r] = ba[tid + 256 * r];
    // overwrite same indices with K (no barrier needed: per-thread same slots)
#pragma unroll
    for (int r = 0; r < 16; r++) ba[tid + 256 * r] = g_QK[1][base + tid + 256 * r];
    __syncthreads();

    fft6(ba, bb, tw, tid, false);                    // Khat in ba

    const float scale = 1.0f / 131072.0f;            // 1/(4096*32)
#pragma unroll
    for (int r = 0; r < 16; r++) {
        int i = tid + 256 * r;
        float2 a = ba[i], q2 = qreg[r];
        ba[i] = make_float2((a.x * q2.x - a.y * q2.y) * scale,
                            (a.x * q2.y + a.y * q2.x) * scale);
    }
    __syncthreads();

    fft6(ba, bb, tw, tid, true);                     // inverse -> ba

#pragma unroll
    for (int r = 0; r < 16; r++) g_P[base + tid + 256 * r] = ba[tid + 256 * r];
}
#define FFT_SMEM ((2048 + 2 * 4096) * (int)sizeof(float2))   // 81920 B

// =====================================================================================
// Kernel 4: irfft-32 over heads + softmax(32) + value gate + residual + LayerNorm(256)
// =====================================================================================
__global__ __launch_bounds__(256) void epilogue(
    const float* __restrict__ vin, const float* __restrict__ gamma,
    const float* __restrict__ beta, float* __restrict__ out)
{
    __shared__ float2 Psm[HEADS * NFREQ * 32];   // [h][f][tok]
    __shared__ float c32[32], s32[32];

    const int tid = threadIdx.x;
    if (tid < 32) {
        float s, c;
        sincospif((float)tid * (1.0f / 16.0f), &s, &c);
        c32[tid] = c; s32[tid] = s;
    }
    const int row0 = blockIdx.x * 32;
    const int b = row0 >> 12, n0 = row0 & (SEQ - 1);

    for (int i = tid; i < HEADS * NFREQ * 32; i += 256) {
        int h = i / (NFREQ * 32);
        int r = i - h * (NFREQ * 32);
        int f = r >> 5, tok = r & 31;
        Psm[i] = g_P[(((size_t)(b * HEADS + h)) * NFREQ + f) * SEQ + n0 + tok];
    }
    __syncthreads();

    const int w = tid >> 5, d = tid & 31;
    const float* __restrict__ vl = g_lin[2];

    for (int it = 0; it < 4; it++) {
        const int tok = w + it * 8;
        const int row = row0 + tok;
        float gh[8];
        float s1 = 0.0f, s2 = 0.0f;
#pragma unroll
        for (int h = 0; h < 8; h++) {
            const float2* Ph = &Psm[h * NFREQ * 32 + tok];
            float acc = Ph[0].x;
            float2 F16 = Ph[16 * 32];
            acc += (d & 1) ? -F16.x : F16.x;
#pragma unroll
            for (int f = 1; f <= 15; f++) {
                float2 F = Ph[f * 32];
                int k2 = (f * d) & 31;
                acc += 2.0f * (F.x * c32[k2] - F.y * s32[k2]);
            }
            float m = acc;
#pragma unroll
            for (int o = 16; o; o >>= 1) m = fmaxf(m, __shfl_xor_sync(0xffffffffu, m, o));
            float e = __expf(acc - m);
            float ss = e;
#pragma unroll
            for (int o = 16; o; o >>= 1) ss += __shfl_xor_sync(0xffffffffu, ss, o);
            float p = e / ss;
            int c = h * 32 + d;
            float vv = vl[(size_t)row * DIM + c];
            float rv = vin[(size_t)row * DIM + c];
            float g = fmaf(vv, p, rv);
            gh[h] = g; s1 += g; s2 = fmaf(g, g, s2);
        }
#pragma unroll
        for (int o = 16; o; o >>= 1) {
            s1 += __shfl_xor_sync(0xffffffffu, s1, o);
            s2 += __shfl_xor_sync(0xffffffffu, s2, o);
        }
        float mean = s1 * (1.0f / 256.0f);
        float var  = s2 * (1.0f / 256.0f) - mean * mean;
        float inv  = rsqrtf(var + 1e-5f);
#pragma unroll
        for (int h = 0; h < 8; h++) {
            int c = h * 32 + d;
            out[(size_t)row * DIM + c] = (gh[h] - mean) * inv * gamma[c] + beta[c];
        }
    }
}

// =====================================================================================
extern "C" void kernel_launch(void* const* d_in, const int* in_sizes, int n_in,
                              void* d_out, int out_size)
{
    const float* q     = (const float*)d_in[0];
    const float* k     = (const float*)d_in[1];
    const float* v     = (const float*)d_in[2];
    const float* Wq    = (const float*)d_in[3];
    const float* bq    = (const float*)d_in[4];
    const float* Wk    = (const float*)d_in[5];
    const float* bk    = (const float*)d_in[6];
    const float* Wv    = (const float*)d_in[7];
    const float* bv    = (const float*)d_in[8];
    const float* gamma = (const float*)d_in[9];
    const float* beta  = (const float*)d_in[10];
    float* out = (float*)d_out;

    cudaFuncSetAttribute(fft_conv, cudaFuncAttributeMaxDynamicSharedMemorySize, FFT_SMEM);
    cudaFuncSetAttribute(gemm_qkv_mma, cudaFuncAttributeMaxDynamicSharedMemorySize, SM_GEMM_TOTAL);

    convert_bf16<<<(NX4 + NW4 + 255) / 256, 256>>>(q, k, v, Wq, Wk, Wv);
    gemm_qkv_mma<<<dim3(ROWS / BM, DIM / BN, 3), 256, SM_GEMM_TOTAL>>>(bq, bk, bv);
    rfft_heads<<<dim3(ROWS / 32, 2), 256>>>();
    fft_conv<<<dim3(NFREQ, BH), 256, FFT_SMEM>>>();
    epilogue<<<ROWS / 32, 256>>>(v, gamma, beta, out);
}

// round 11
// speedup vs baseline: 1.6025x; 1.0610x over previous
#include <cuda_runtime.h>
#include <cuda_bf16.h>
#include <math_constants.h>
#include <cstdint>

// Problem constants
#define BATCH   8
#define SEQ     4096
#define DIM     256
#define HEADS   8
#define HD      32
#define NFREQ   17          // HD/2 + 1
#define ROWS    (BATCH*SEQ) // 32768
#define BH      (BATCH*HEADS) // 64

typedef unsigned long long u64;

// ---------------- scratch (static __device__ — no allocations allowed) ----------------
__device__ float  g_lin[3][(size_t)ROWS * DIM];            // ql, kl, vl
__device__ float2 g_QK[2][(size_t)BH * NFREQ * SEQ];       // Qhat, Khat
__device__ float2 g_P[(size_t)BH * NFREQ * SEQ];           // product after inverse seq-FFT
__device__ __nv_bfloat16 g_xhi[3][(size_t)ROWS * DIM];     // bf16 hi/lo split of q,k,v
__device__ __nv_bfloat16 g_xlo[3][(size_t)ROWS * DIM];
__device__ __nv_bfloat16 g_whi[3][DIM * DIM];              // and of Wq,Wk,Wv
__device__ __nv_bfloat16 g_wlo[3][DIM * DIM];

// ======================= small asm helpers ========================
__device__ __forceinline__ uint32_t smem_u32(const void* p) {
    uint32_t a;
    asm("{ .reg .u64 t; cvta.to.shared.u64 t, %1; cvt.u32.u64 %0, t; }" : "=r"(a) : "l"(p));
    return a;
}
__device__ __forceinline__ void cp16(uint32_t dst, const void* src) {
    asm volatile("cp.async.ca.shared.global [%0], [%1], 16;" :: "r"(dst), "l"(src));
}
__device__ __forceinline__ void cp_commit() { asm volatile("cp.async.commit_group;"); }
__device__ __forceinline__ void cp_wait0()  { asm volatile("cp.async.wait_group 0;"); }
__device__ __forceinline__ void ldsm4(uint32_t* r, uint32_t addr) {
    asm volatile("ldmatrix.sync.aligned.m8n8.x4.shared.b16 {%0,%1,%2,%3}, [%4];"
                 : "=r"(r[0]), "=r"(r[1]), "=r"(r[2]), "=r"(r[3]) : "r"(addr));
}
__device__ __forceinline__ void mma16816(float* c, const uint32_t* a, const uint32_t* b) {
    asm volatile(
        "mma.sync.aligned.m16n8k16.row.col.f32.bf16.bf16.f32 "
        "{%0,%1,%2,%3}, {%4,%5,%6,%7}, {%8,%9}, {%0,%1,%2,%3};"
        : "+f"(c[0]), "+f"(c[1]), "+f"(c[2]), "+f"(c[3])
        : "r"(a[0]), "r"(a[1]), "r"(a[2]), "r"(a[3]), "r"(b[0]), "r"(b[1]));
}
__device__ __forceinline__ void cvt_hi_lo(float4 xv, u64& hw, u64& lw) {
    __nv_bfloat16 h0 = __float2bfloat16_rn(xv.x);
    __nv_bfloat16 h1 = __float2bfloat16_rn(xv.y);
    __nv_bfloat16 h2 = __float2bfloat16_rn(xv.z);
    __nv_bfloat16 h3 = __float2bfloat16_rn(xv.w);
    __nv_bfloat16 l0 = __float2bfloat16_rn(xv.x - __bfloat162float(h0));
    __nv_bfloat16 l1 = __float2bfloat16_rn(xv.y - __bfloat162float(h1));
    __nv_bfloat16 l2 = __float2bfloat16_rn(xv.z - __bfloat162float(h2));
    __nv_bfloat16 l3 = __float2bfloat16_rn(xv.w - __bfloat162float(h3));
    hw = (u64)__bfloat16_as_ushort(h0) | ((u64)__bfloat16_as_ushort(h1) << 16)
       | ((u64)__bfloat16_as_ushort(h2) << 32) | ((u64)__bfloat16_as_ushort(h3) << 48);
    lw = (u64)__bfloat16_as_ushort(l0) | ((u64)__bfloat16_as_ushort(l1) << 16)
       | ((u64)__bfloat16_as_ushort(l2) << 32) | ((u64)__bfloat16_as_ushort(l3) << 48);
}

// =====================================================================================
// Kernel 0: fp32 -> bf16 hi/lo split for X (q,k,v) and W (Wq,Wk,Wv). Pure streaming.
// =====================================================================================
#define NX4 (3 * ROWS * DIM / 4)
#define NW4 (3 * DIM * DIM / 4)
__global__ __launch_bounds__(256) void convert_bf16(
    const float* __restrict__ q, const float* __restrict__ k, const float* __restrict__ v,
    const float* __restrict__ Wq, const float* __restrict__ Wk, const float* __restrict__ Wv)
{
    const int idx = blockIdx.x * 256 + threadIdx.x;
    u64 hw, lw;
    if (idx < NX4) {
        const int per = ROWS * DIM / 4;
        const int z = idx / per, off = idx - z * per;
        const float* src = (z == 0) ? q : (z == 1) ? k : v;
        cvt_hi_lo(reinterpret_cast<const float4*>(src)[off], hw, lw);
        reinterpret_cast<u64*>(g_xhi[z])[off] = hw;
        reinterpret_cast<u64*>(g_xlo[z])[off] = lw;
    } else if (idx < NX4 + NW4) {
        const int per = DIM * DIM / 4;
        const int iw = idx - NX4;
        const int z = iw / per, off = iw - z * per;
        const float* src = (z == 0) ? Wq : (z == 1) ? Wk : Wv;
        cvt_hi_lo(reinterpret_cast<const float4*>(src)[off], hw, lw);
        reinterpret_cast<u64*>(g_whi[z])[off] = hw;
        reinterpret_cast<u64*>(g_wlo[z])[off] = lw;
    }
}

// =====================================================================================
// Kernel 1: QKV GEMM on mma.sync, operands pre-split bf16, cp.async double buffer,
// ldmatrix fragments. CTA: M=256 x N=128, K chunks of 32. 8 warps = 4(M) x 2(N).
// =====================================================================================
#define BM 256
#define BN 128
#define BK 32
#define RB 80                 // bytes per SMEM row (40 bf16)
#define OF_AHI 0
#define OF_ALO (BM * RB)
#define OF_BHI (2 * BM * RB)
#define OF_BLO (2 * BM * RB + BN * RB)
#define BUF_SZ (2 * BM * RB + 2 * BN * RB)
#define SM_GEMM_TOTAL (2 * BUF_SZ)         // 122880

__device__ __forceinline__ void gemm_load_chunk(
    uint32_t buf, int tid, int kk, int row0, int col0,
    const __nv_bfloat16* Xhi, const __nv_bfloat16* Xlo,
    const __nv_bfloat16* Whi, const __nv_bfloat16* Wlo)
{
#pragma unroll
    for (int i = 0; i < 4; i++) {
        int idx = tid + 256 * i;
        int row = idx >> 2, j = idx & 3;
        size_t g = (size_t)(row0 + row) * DIM + kk + j * 8;
        uint32_t d = buf + row * RB + j * 16;
        cp16(d + OF_AHI, Xhi + g);
        cp16(d + OF_ALO, Xlo + g);
    }
#pragma unroll
    for (int i = 0; i < 2; i++) {
        int idx = tid + 256 * i;
        int row = idx >> 2, j = idx & 3;
        size_t g = (size_t)(col0 + row) * DIM + kk + j * 8;
        uint32_t d = buf + row * RB + j * 16;
        cp16(d + OF_BHI, Whi + g);
        cp16(d + OF_BLO, Wlo + g);
    }
}

__global__ __launch_bounds__(256) void gemm_qkv_mma(
    const float* __restrict__ bq, const float* __restrict__ bk, const float* __restrict__ bv)
{
    extern __shared__ unsigned char smem[];
    const uint32_t sbase = smem_u32(smem);

    const int z = blockIdx.z;
    const __nv_bfloat16* Xhi = g_xhi[z];
    const __nv_bfloat16* Xlo = g_xlo[z];
    const __nv_bfloat16* Whi = g_whi[z];
    const __nv_bfloat16* Wlo = g_wlo[z];
    const float* bias = (z == 0) ? bq : (z == 1) ? bk : bv;
    float* out = g_lin[z];

    const int tid   = threadIdx.x;
    const int wid   = tid >> 5;
    const int lane  = tid & 31;
    const int group = lane >> 2;
    const int tig   = lane & 3;
    const int warpM = wid >> 1;
    const int warpN = wid & 1;
    const int row0  = blockIdx.x * BM;
    const int col0  = blockIdx.y * BN;

    const int tile = lane >> 3, ti = lane & 7;
    const uint32_t rowA = (uint32_t)(warpM * 64 + ((tile & 1) << 3) + ti) * RB;
    const uint32_t rowB = (uint32_t)(warpN * 64 + ((tile & 1) << 3) + ti) * RB;
    const uint32_t colT = (uint32_t)((tile >> 1) << 3) * 2;

    float acc[4][8][4];
#pragma unroll
    for (int mi = 0; mi < 4; mi++)
#pragma unroll
        for (int ni = 0; ni < 8; ni++)
#pragma unroll
            for (int r = 0; r < 4; r++) acc[mi][ni][r] = 0.0f;

    gemm_load_chunk(sbase, tid, 0, row0, col0, Xhi, Xlo, Whi, Wlo);
    cp_commit();

#pragma unroll 1
    for (int c = 0; c < DIM / BK; c++) {
        cp_wait0();
        __syncthreads();
        if (c + 1 < DIM / BK) {
            gemm_load_chunk(sbase + ((c + 1) & 1) * BUF_SZ, tid, (c + 1) * BK,
                            row0, col0, Xhi, Xlo, Whi, Wlo);
            cp_commit();
        }
        const uint32_t buf = sbase + (c & 1) * BUF_SZ;

#pragma unroll
        for (int ks = 0; ks < 2; ks++) {
            const uint32_t kb = (uint32_t)(ks * 32) + colT;
            uint32_t ahi[4][4], alo[4][4], bhi[4][4], blo[4][4];
#pragma unroll
            for (int mi = 0; mi < 4; mi++) {
                ldsm4(ahi[mi], buf + OF_AHI + rowA + mi * (16 * RB) + kb);
                ldsm4(alo[mi], buf + OF_ALO + rowA + mi * (16 * RB) + kb);
            }
#pragma unroll
            for (int p = 0; p < 4; p++) {
                ldsm4(bhi[p], buf + OF_BHI + rowB + p * (16 * RB) + kb);
                ldsm4(blo[p], buf + OF_BLO + rowB + p * (16 * RB) + kb);
            }
#pragma unroll
            for (int mi = 0; mi < 4; mi++) {
#pragma unroll
                for (int ni = 0; ni < 8; ni++) {
                    const int p = ni >> 1, s = ni & 1;
                    uint32_t bh[2] = {bhi[p][s], bhi[p][2 + s]};
                    uint32_t bl[2] = {blo[p][s], blo[p][2 + s]};
                    mma16816(acc[mi][ni], ahi[mi], bh);
                    mma16816(acc[mi][ni], ahi[mi], bl);
                    mma16816(acc[mi][ni], alo[mi], bh);
                }
            }
        }
        __syncthreads();
    }

    float2 bb[8];
#pragma unroll
    for (int ni = 0; ni < 8; ni++)
        bb[ni] = *reinterpret_cast<const float2*>(&bias[col0 + warpN * 64 + ni * 8 + tig * 2]);

#pragma unroll
    for (int mi = 0; mi < 4; mi++) {
        int rg = row0 + warpM * 64 + mi * 16 + group;
#pragma unroll
        for (int ni = 0; ni < 8; ni++) {
            int cg = col0 + warpN * 64 + ni * 8 + tig * 2;
            *reinterpret_cast<float2*>(&out[(size_t)rg * DIM + cg]) =
                make_float2(acc[mi][ni][0] + bb[ni].x, acc[mi][ni][1] + bb[ni].y);
            *reinterpret_cast<float2*>(&out[(size_t)(rg + 8) * DIM + cg]) =
                make_float2(acc[mi][ni][2] + bb[ni].x, acc[mi][ni][3] + bb[ni].y);
        }
    }
}

// =====================================================================================
// Kernel 2: rfft over head_dim (32 -> 17 complex bins) for ql and kl.
// =====================================================================================
__global__ __launch_bounds__(256) void rfft_heads()
{
    const int which = blockIdx.y;            // 0 -> Q, 1 -> K
    const float* __restrict__ src = g_lin[which];
    float2* __restrict__ dst = g_QK[which];

    __shared__ float xs[32 * 264];
    __shared__ float twc[32], tws[32];

    const int tid = threadIdx.x;
    if (tid < 32) {
        float s, c;
        sincospif((float)tid * (1.0f / 16.0f), &s, &c);
        twc[tid] = c; tws[tid] = s;
    }
    const int row0 = blockIdx.x * 32;
    for (int i = tid; i < 32 * 256; i += 256) {
        int tok = i >> 8, cc = i & 255;
        xs[tok * 264 + (cc >> 5) * 33 + (cc & 31)] = src[(size_t)row0 * DIM + i];
    }
    __syncthreads();

    const int tok = tid >> 3, h = tid & 7;
    float xr[32];
#pragma unroll
    for (int d = 0; d < 32; d++) xr[d] = xs[tok * 264 + h * 33 + d];

    const int b  = row0 >> 12;
    const int n  = (row0 & (SEQ - 1)) + tok;
    const int bh = b * HEADS + h;

    for (int f = 0; f < NFREQ; f++) {
        float re = 0.0f, im = 0.0f;
#pragma unroll
        for (int d = 0; d < 32; d++) {
            int k2 = (f * d) & 31;
            re = fmaf(xr[d], twc[k2], re);
            im = fmaf(xr[d], -tws[k2], im);
        }
        dst[((size_t)bh * NFREQ + f) * SEQ + n] = make_float2(re, im);
    }
}

// =====================================================================================
// Kernel 3: per (b,h,f) column: FFT4096(Q), FFT4096(K), pointwise mult (scaled),
// inverse FFT4096 -> g_P.  Radix-8 Stockham (4 stages), Qhat in registers.
// SMEM: tw(16KB) + 2 work buffers(64KB) = 80KB -> 2 CTAs/SM.
// =====================================================================================
__device__ __forceinline__ float2 cmulf(float2 a, float2 b) {
    return make_float2(a.x * b.x - a.y * b.y, a.x * b.y + a.y * b.x);
}
// rot(v) = -i*v (fwd) / +i*v (inv)
template<bool INV>
__device__ __forceinline__ float2 rot90(float2 v) {
    return INV ? make_float2(-v.y, v.x) : make_float2(v.y, -v.x);
}
// w8mul(v) = W_8^1 * v  (W_8^1 = (c,-c) fwd, (c,c) inv), c = sqrt(2)/2
template<bool INV>
__device__ __forceinline__ float2 w8mul(float2 v) {
    const float c = 0.70710678118654752f;
    return INV ? make_float2(c * (v.x - v.y), c * (v.x + v.y))
               : make_float2(c * (v.x + v.y), c * (v.y - v.x));
}

template<bool INV>
__device__ __forceinline__ void fft8x(float2* __restrict__ xin, float2* __restrict__ yin,
                                      const float2* __restrict__ tw, int tid)
{
    float2* a = xin; float2* b = yin;
#pragma unroll 1
    for (int st = 0; st < 4; st++) {
        const int S = 1 << (3 * st);          // 1, 8, 64, 512
#pragma unroll
        for (int it = 0; it < 2; it++) {
            const int j  = tid + (it << 8);   // 0..511
            const int q  = j & (S - 1);
            const int pS = j - q;
            float2 x0 = a[j],        x1 = a[j + 512],  x2 = a[j + 1024], x3 = a[j + 1536];
            float2 x4 = a[j + 2048], x5 = a[j + 2560], x6 = a[j + 3072], x7 = a[j + 3584];
            // DFT8 via even/odd DFT4s (even: x0,x2,x4,x6 ; odd: x1,x3,x5,x7)
            float2 t0 = make_float2(x0.x + x4.x, x0.y + x4.y);
            float2 t1 = make_float2(x0.x - x4.x, x0.y - x4.y);
            float2 t2 = make_float2(x2.x + x6.x, x2.y + x6.y);
            float2 t3 = rot90<INV>(make_float2(x2.x - x6.x, x2.y - x6.y));
            float2 e0 = make_float2(t0.x + t2.x, t0.y + t2.y);
            float2 e2 = make_float2(t0.x - t2.x, t0.y - t2.y);
            float2 e1 = make_float2(t1.x + t3.x, t1.y + t3.y);
            float2 e3 = make_float2(t1.x - t3.x, t1.y - t3.y);
            float2 s0 = make_float2(x1.x + x5.x, x1.y + x5.y);
            float2 s1 = make_float2(x1.x - x5.x, x1.y - x5.y);
            float2 s2 = make_float2(x3.x + x7.x, x3.y + x7.y);
            float2 s3 = rot90<INV>(make_float2(x3.x - x7.x, x3.y - x7.y));
            float2 o0 = make_float2(s0.x + s2.x, s0.y + s2.y);
            float2 o2 = make_float2(s0.x - s2.x, s0.y - s2.y);
            float2 o1 = make_float2(s1.x + s3.x, s1.y + s3.y);
            float2 o3 = make_float2(s1.x - s3.x, s1.y - s3.y);
            // combine: u_m = W_8^m * o_m
            float2 u1 = w8mul<INV>(o1);
            float2 u2 = rot90<INV>(o2);
            float2 u3 = rot90<INV>(w8mul<INV>(o3));
            float2 X0 = make_float2(e0.x + o0.x, e0.y + o0.y);
            float2 X4 = make_float2(e0.x - o0.x, e0.y - o0.y);
            float2 X1 = make_float2(e1.x + u1.x, e1.y + u1.y);
            float2 X5 = make_float2(e1.x - u1.x, e1.y - u1.y);
            float2 X2 = make_float2(e2.x + u2.x, e2.y + u2.y);
            float2 X6 = make_float2(e2.x - u2.x, e2.y - u2.y);
            float2 X3 = make_float2(e3.x + u3.x, e3.y + u3.y);
            float2 X7 = make_float2(e3.x - u3.x, e3.y - u3.y);
            // twiddles W^{m*pS}: load w1,w2; chain the rest (conjugate for inverse)
            float2 w1 = tw[pS];
            float2 w2 = tw[2 * pS];
            if (INV) { w1.y = -w1.y; w2.y = -w2.y; }
            float2 w3 = cmulf(w2, w1);
            float2 w4 = cmulf(w2, w2);
            float2 w5 = cmulf(w4, w1);
            float2 w6 = cmulf(w4, w2);
            float2 w7 = cmulf(w4, w3);
            const int ob = 8 * pS + q;
            b[ob]         = X0;
            b[ob + S]     = cmulf(X1, w1);
            b[ob + 2 * S] = cmulf(X2, w2);
            b[ob + 3 * S] = cmulf(X3, w3);
            b[ob + 4 * S] = cmulf(X4, w4);
            b[ob + 5 * S] = cmulf(X5, w5);
            b[ob + 6 * S] = cmulf(X6, w6);
            b[ob + 7 * S] = cmulf(X7, w7);
        }
        __syncthreads();
        float2* tmp = a; a = b; b = tmp;
    }
    // 4 swaps -> result back in xin
}

__global__ __launch_bounds__(256) void fft_conv()
{
    extern __shared__ unsigned char smraw[];
    float2* tw = reinterpret_cast<float2*>(smraw);   // 2048
    float2* ba = tw + 2048;                          // 4096 work A
    float2* bb = ba + 4096;                          // 4096 work B

    const int tid = threadIdx.x;
    const int f   = blockIdx.x;      // 0..16
    const int bh  = blockIdx.y;      // 0..63
    const size_t base = ((size_t)bh * NFREQ + f) * SEQ;

    for (int i = tid; i < 2048; i += 256) {
        float s, c;
        sincospif((float)i * (1.0f / 2048.0f), &s, &c);
        tw[i] = make_float2(c, -s);
    }
#pragma unroll
    for (int r = 0; r < 16; r++) ba[tid + 256 * r] = g_QK[0][base + tid + 256 * r];
    __syncthreads();

    fft8x<false>(ba, bb, tw, tid);                   // Qhat in ba

    // stash Qhat in registers (thread owns indices tid + 256*r)
    float2 qreg[16];
#pragma unroll
    for (int r = 0; r < 16; r++) qreg[r] = ba[tid + 256 * r];
#pragma unroll
    for (int r = 0; r < 16; r++) ba[tid + 256 * r] = g_QK[1][base + tid + 256 * r];
    __syncthreads();

    fft8x<false>(ba, bb, tw, tid);                   // Khat in ba

    const float scale = 1.0f / 131072.0f;            // 1/(4096*32)
#pragma unroll
    for (int r = 0; r < 16; r++) {
        int i = tid + 256 * r;
        float2 a = ba[i], q2 = qreg[r];
        ba[i] = make_float2((a.x * q2.x - a.y * q2.y) * scale,
                            (a.x * q2.y + a.y * q2.x) * scale);
    }
    __syncthreads();

    fft8x<true>(ba, bb, tw, tid);                    // inverse -> ba

#pragma unroll
    for (int r = 0; r < 16; r++) g_P[base + tid + 256 * r] = ba[tid + 256 * r];
}
#define FFT_SMEM ((2048 + 2 * 4096) * (int)sizeof(float2))   // 81920 B

// =====================================================================================
// Kernel 4: irfft-32 over heads + softmax(32) + value gate + residual + LayerNorm(256)
// Phase-batched: all 8 head-softmax reductions interleaved for SHFL latency hiding.
// =====================================================================================
__global__ __launch_bounds__(256) void epilogue(
    const float* __restrict__ vin, const float* __restrict__ gamma,
    const float* __restrict__ beta, float* __restrict__ out)
{
    __shared__ float2 Psm[HEADS * NFREQ * 32];   // [h][f][tok]
    __shared__ float c32[32], s32[32];

    const int tid = threadIdx.x;
    if (tid < 32) {
        float s, c;
        sincospif((float)tid * (1.0f / 16.0f), &s, &c);
        c32[tid] = c; s32[tid] = s;
    }
    const int row0 = blockIdx.x * 32;
    const int b = row0 >> 12, n0 = row0 & (SEQ - 1);

    for (int i = tid; i < HEADS * NFREQ * 32; i += 256) {
        int h = i / (NFREQ * 32);
        int r = i - h * (NFREQ * 32);
        int f = r >> 5, tok = r & 31;
        Psm[i] = g_P[(((size_t)(b * HEADS + h)) * NFREQ + f) * SEQ + n0 + tok];
    }
    __syncthreads();

    const int w = tid >> 5, d = tid & 31;
    const float* __restrict__ vl = g_lin[2];

    for (int it = 0; it < 4; it++) {
        const int tok = w + it * 8;
        const int row = row0 + tok;

        // phase 1: irfft-32 logits for all 8 heads
        float acc[8];
#pragma unroll
        for (int h = 0; h < 8; h++) {
            const float2* Ph = &Psm[h * NFREQ * 32 + tok];
            float a = Ph[0].x;                         // f = 0 (real)
            float2 F16 = Ph[16 * 32];
            a += (d & 1) ? -F16.x : F16.x;             // Nyquist (real)
#pragma unroll
            for (int f = 1; f <= 15; f++) {
                float2 F = Ph[f * 32];
                int k2 = (f * d) & 31;
                a += 2.0f * (F.x * c32[k2] - F.y * s32[k2]);
            }
            acc[h] = a;
        }

        // phase 2: batched max-reduction (8 independent chains interleaved)
        float m[8];
#pragma unroll
        for (int h = 0; h < 8; h++) m[h] = acc[h];
#pragma unroll
        for (int o = 16; o; o >>= 1)
#pragma unroll
            for (int h = 0; h < 8; h++)
                m[h] = fmaxf(m[h], __shfl_xor_sync(0xffffffffu, m[h], o));

        // phase 3: exp
        float e[8];
#pragma unroll
        for (int h = 0; h < 8; h++) e[h] = __expf(acc[h] - m[h]);

        // phase 4: batched sum-reduction
        float ss[8];
#pragma unroll
        for (int h = 0; h < 8; h++) ss[h] = e[h];
#pragma unroll
        for (int o = 16; o; o >>= 1)
#pragma unroll
            for (int h = 0; h < 8; h++)
                ss[h] += __shfl_xor_sync(0xffffffffu, ss[h], o);

        // phase 5: gate + residual; LN stats
        float gh[8];
        float s1 = 0.0f, s2 = 0.0f;
#pragma unroll
        for (int h = 0; h < 8; h++) {
            float p = __fdividef(e[h], ss[h]);
            int c = h * 32 + d;
            float vv = vl[(size_t)row * DIM + c];
            float rv = vin[(size_t)row * DIM + c];
            float g = fmaf(vv, p, rv);
            gh[h] = g; s1 += g; s2 = fmaf(g, g, s2);
        }
#pragma unroll
        for (int o = 16; o; o >>= 1) {
            s1 += __shfl_xor_sync(0xffffffffu, s1, o);
            s2 += __shfl_xor_sync(0xffffffffu, s2, o);
        }
        float mean = s1 * (1.0f / 256.0f);
        float var  = s2 * (1.0f / 256.0f) - mean * mean;
        float inv  = rsqrtf(var + 1e-5f);
#pragma unroll
        for (int h = 0; h < 8; h++) {
            int c = h * 32 + d;
            out[(size_t)row * DIM + c] = (gh[h] - mean) * inv * gamma[c] + beta[c];
        }
    }
}

// =====================================================================================
extern "C" void kernel_launch(void* const* d_in, const int* in_sizes, int n_in,
                              void* d_out, int out_size)
{
    const float* q     = (const float*)d_in[0];
    const float* k     = (const float*)d_in[1];
    const float* v     = (const float*)d_in[2];
    const float* Wq    = (const float*)d_in[3];
    const float* bq    = (const float*)d_in[4];
    const float* Wk    = (const float*)d_in[5];
    const float* bk    = (const float*)d_in[6];
    const float* Wv    = (const float*)d_in[7];
    const float* bv    = (const float*)d_in[8];
    const float* gamma = (const float*)d_in[9];
    const float* beta  = (const float*)d_in[10];
    float* out = (float*)d_out;

    cudaFuncSetAttribute(fft_conv, cudaFuncAttributeMaxDynamicSharedMemorySize, FFT_SMEM);
    cudaFuncSetAttribute(gemm_qkv_mma, cudaFuncAttributeMaxDynamicSharedMemorySize, SM_GEMM_TOTAL);

    convert_bf16<<<(NX4 + NW4 + 255) / 256, 256>>>(q, k, v, Wq, Wk, Wv);
    gemm_qkv_mma<<<dim3(ROWS / BM, DIM / BN, 3), 256, SM_GEMM_TOTAL>>>(bq, bk, bv);
    rfft_heads<<<dim3(ROWS / 32, 2), 256>>>();
    fft_conv<<<dim3(NFREQ, BH), 256, FFT_SMEM>>>();
    epilogue<<<ROWS / 32, 256>>>(v, gamma, beta, out);
}

// round 15
// speedup vs baseline: 1.7106x; 1.0675x over previous
#include <cuda_runtime.h>
#include <cuda_bf16.h>
#include <math_constants.h>
#include <cstdint>

// Problem constants
#define BATCH   8
#define SEQ     4096
#define DIM     256
#define HEADS   8
#define HD      32
#define NFREQ   17          // HD/2 + 1
#define ROWS    (BATCH*SEQ) // 32768
#define BH      (BATCH*HEADS) // 64

typedef unsigned long long u64;

// ---------------- scratch (static __device__ — no allocations allowed) ----------------
__device__ float  g_lin[3][(size_t)ROWS * DIM];            // ql, kl, vl
__device__ float2 g_QK[2][(size_t)BH * NFREQ * SEQ];       // Qhat, Khat
__device__ float2 g_P[(size_t)BH * NFREQ * SEQ];           // product after inverse seq-FFT
__device__ __nv_bfloat16 g_xhi[3][(size_t)ROWS * DIM];     // bf16 hi/lo split of q,k,v
__device__ __nv_bfloat16 g_xlo[3][(size_t)ROWS * DIM];
__device__ __nv_bfloat16 g_whi[3][DIM * DIM];              // and of Wq,Wk,Wv
__device__ __nv_bfloat16 g_wlo[3][DIM * DIM];

// ======================= small asm helpers ========================
__device__ __forceinline__ uint32_t smem_u32(const void* p) {
    uint32_t a;
    asm("{ .reg .u64 t; cvta.to.shared.u64 t, %1; cvt.u32.u64 %0, t; }" : "=r"(a) : "l"(p));
    return a;
}
__device__ __forceinline__ void cp16(uint32_t dst, const void* src) {
    asm volatile("cp.async.ca.shared.global [%0], [%1], 16;" :: "r"(dst), "l"(src));
}
__device__ __forceinline__ void cp_commit() { asm volatile("cp.async.commit_group;"); }
__device__ __forceinline__ void cp_wait0()  { asm volatile("cp.async.wait_group 0;"); }
__device__ __forceinline__ void ldsm4(uint32_t* r, uint32_t addr) {
    asm volatile("ldmatrix.sync.aligned.m8n8.x4.shared.b16 {%0,%1,%2,%3}, [%4];"
                 : "=r"(r[0]), "=r"(r[1]), "=r"(r[2]), "=r"(r[3]) : "r"(addr));
}
__device__ __forceinline__ void mma16816(float* c, const uint32_t* a, const uint32_t* b) {
    asm volatile(
        "mma.sync.aligned.m16n8k16.row.col.f32.bf16.bf16.f32 "
        "{%0,%1,%2,%3}, {%4,%5,%6,%7}, {%8,%9}, {%0,%1,%2,%3};"
        : "+f"(c[0]), "+f"(c[1]), "+f"(c[2]), "+f"(c[3])
        : "r"(a[0]), "r"(a[1]), "r"(a[2]), "r"(a[3]), "r"(b[0]), "r"(b[1]));
}
__device__ __forceinline__ void cvt_hi_lo(float4 xv, u64& hw, u64& lw) {
    __nv_bfloat16 h0 = __float2bfloat16_rn(xv.x);
    __nv_bfloat16 h1 = __float2bfloat16_rn(xv.y);
    __nv_bfloat16 h2 = __float2bfloat16_rn(xv.z);
    __nv_bfloat16 h3 = __float2bfloat16_rn(xv.w);
    __nv_bfloat16 l0 = __float2bfloat16_rn(xv.x - __bfloat162float(h0));
    __nv_bfloat16 l1 = __float2bfloat16_rn(xv.y - __bfloat162float(h1));
    __nv_bfloat16 l2 = __float2bfloat16_rn(xv.z - __bfloat162float(h2));
    __nv_bfloat16 l3 = __float2bfloat16_rn(xv.w - __bfloat162float(h3));
    hw = (u64)__bfloat16_as_ushort(h0) | ((u64)__bfloat16_as_ushort(h1) << 16)
       | ((u64)__bfloat16_as_ushort(h2) << 32) | ((u64)__bfloat16_as_ushort(h3) << 48);
    lw = (u64)__bfloat16_as_ushort(l0) | ((u64)__bfloat16_as_ushort(l1) << 16)
       | ((u64)__bfloat16_as_ushort(l2) << 32) | ((u64)__bfloat16_as_ushort(l3) << 48);
}

// =====================================================================================
// Kernel 0: fp32 -> bf16 hi/lo split for X (q,k,v) and W (Wq,Wk,Wv). Pure streaming.
// =====================================================================================
#define NX4 (3 * ROWS * DIM / 4)
#define NW4 (3 * DIM * DIM / 4)
__global__ __launch_bounds__(256) void convert_bf16(
    const float* __restrict__ q, const float* __restrict__ k, const float* __restrict__ v,
    const float* __restrict__ Wq, const float* __restrict__ Wk, const float* __restrict__ Wv)
{
    const int idx = blockIdx.x * 256 + threadIdx.x;
    u64 hw, lw;
    if (idx < NX4) {
        const int per = ROWS * DIM / 4;
        const int z = idx / per, off = idx - z * per;
        const float* src = (z == 0) ? q : (z == 1) ? k : v;
        cvt_hi_lo(reinterpret_cast<const float4*>(src)[off], hw, lw);
        reinterpret_cast<u64*>(g_xhi[z])[off] = hw;
        reinterpret_cast<u64*>(g_xlo[z])[off] = lw;
    } else if (idx < NX4 + NW4) {
        const int per = DIM * DIM / 4;
        const int iw = idx - NX4;
        const int z = iw / per, off = iw - z * per;
        const float* src = (z == 0) ? Wq : (z == 1) ? Wk : Wv;
        cvt_hi_lo(reinterpret_cast<const float4*>(src)[off], hw, lw);
        reinterpret_cast<u64*>(g_whi[z])[off] = hw;
        reinterpret_cast<u64*>(g_wlo[z])[off] = lw;
    }
}

// =====================================================================================
// Kernel 1: QKV GEMM on mma.sync, pre-split bf16 operands, cp.async double buffer,
// ldmatrix fragments. CTA: M=128 x N=128 (2 CTAs/SM). 8 warps = 2(M) x 4(N),
// warp tile 64x32. Products hi*hi + hi*lo + lo*hi; A hi/lo fragments sequential
// (one 16-reg fragment set reused) to fit the 128-reg / 2-CTA occupancy budget.
// =====================================================================================
#define BM 128
#define BN 128
#define BK 32
#define RB 80                 // bytes per SMEM row (40 bf16)
#define OF_AHI 0
#define OF_ALO (BM * RB)                   // 10240
#define OF_BHI (2 * BM * RB)               // 20480
#define OF_BLO (2 * BM * RB + BN * RB)     // 30720
#define BUF_SZ (2 * BM * RB + 2 * BN * RB) // 40960
#define SM_GEMM_TOTAL (2 * BUF_SZ)         // 81920

__device__ __forceinline__ void gemm_load_chunk(
    uint32_t buf, int tid, int kk, int row0, int col0,
    const __nv_bfloat16* Xhi, const __nv_bfloat16* Xlo,
    const __nv_bfloat16* Whi, const __nv_bfloat16* Wlo)
{
#pragma unroll
    for (int i = 0; i < 2; i++) {                 // A: 128 rows x 64B, hi + lo
        int idx = tid + 256 * i;
        int row = idx >> 2, j = idx & 3;
        size_t g = (size_t)(row0 + row) * DIM + kk + j * 8;
        uint32_t d = buf + row * RB + j * 16;
        cp16(d + OF_AHI, Xhi + g);
        cp16(d + OF_ALO, Xlo + g);
    }
#pragma unroll
    for (int i = 0; i < 2; i++) {                 // B: 128 rows x 64B, hi + lo
        int idx = tid + 256 * i;
        int row = idx >> 2, j = idx & 3;
        size_t g = (size_t)(col0 + row) * DIM + kk + j * 8;
        uint32_t d = buf + row * RB + j * 16;
        cp16(d + OF_BHI, Whi + g);
        cp16(d + OF_BLO, Wlo + g);
    }
}

__global__ __launch_bounds__(256, 2) void gemm_qkv_mma(
    const float* __restrict__ bq, const float* __restrict__ bk, const float* __restrict__ bv)
{
    extern __shared__ unsigned char smem[];
    const uint32_t sbase = smem_u32(smem);

    const int z = blockIdx.z;
    const __nv_bfloat16* Xhi = g_xhi[z];
    const __nv_bfloat16* Xlo = g_xlo[z];
    const __nv_bfloat16* Whi = g_whi[z];
    const __nv_bfloat16* Wlo = g_wlo[z];
    const float* bias = (z == 0) ? bq : (z == 1) ? bk : bv;
    float* out = g_lin[z];

    const int tid   = threadIdx.x;
    const int wid   = tid >> 5;
    const int lane  = tid & 31;
    const int group = lane >> 2;
    const int tig   = lane & 3;
    const int warpM = wid >> 2;       // 0..1 (x64 rows)
    const int warpN = wid & 3;        // 0..3 (x32 cols)
    const int row0  = blockIdx.x * BM;
    const int col0  = blockIdx.y * BN;

    const int tile = lane >> 3, ti = lane & 7;
    const uint32_t rowA = (uint32_t)(warpM * 64 + ((tile & 1) << 3) + ti) * RB;
    const uint32_t rowB = (uint32_t)(warpN * 32 + ((tile & 1) << 3) + ti) * RB;
    const uint32_t colT = (uint32_t)((tile >> 1) << 3) * 2;

    float acc[4][4][4];
#pragma unroll
    for (int mi = 0; mi < 4; mi++)
#pragma unroll
        for (int ni = 0; ni < 4; ni++)
#pragma unroll
            for (int r = 0; r < 4; r++) acc[mi][ni][r] = 0.0f;

    gemm_load_chunk(sbase, tid, 0, row0, col0, Xhi, Xlo, Whi, Wlo);
    cp_commit();

#pragma unroll 1
    for (int c = 0; c < DIM / BK; c++) {
        cp_wait0();
        __syncthreads();
        if (c + 1 < DIM / BK) {
            gemm_load_chunk(sbase + ((c + 1) & 1) * BUF_SZ, tid, (c + 1) * BK,
                            row0, col0, Xhi, Xlo, Whi, Wlo);
            cp_commit();
        }
        const uint32_t buf = sbase + (c & 1) * BUF_SZ;

#pragma unroll
        for (int ks = 0; ks < 2; ks++) {
            const uint32_t kb = (uint32_t)(ks * 32) + colT;
            uint32_t afr[4][4], bhi[2][4], blo[2][4];
            // B fragments (32 N-rows = 2 x ldsm4 each for hi/lo)
#pragma unroll
            for (int p = 0; p < 2; p++) {
                ldsm4(bhi[p], buf + OF_BHI + rowB + p * (16 * RB) + kb);
                ldsm4(blo[p], buf + OF_BLO + rowB + p * (16 * RB) + kb);
            }
            // A-hi fragments, then hi*hi and hi*lo
#pragma unroll
            for (int mi = 0; mi < 4; mi++)
                ldsm4(afr[mi], buf + OF_AHI + rowA + mi * (16 * RB) + kb);
#pragma unroll
            for (int mi = 0; mi < 4; mi++) {
#pragma unroll
                for (int ni = 0; ni < 4; ni++) {
                    const int p = ni >> 1, s = ni & 1;
                    uint32_t bh[2] = {bhi[p][s], bhi[p][2 + s]};
                    uint32_t bl[2] = {blo[p][s], blo[p][2 + s]};
                    mma16816(acc[mi][ni], afr[mi], bh);   // hi*hi
                    mma16816(acc[mi][ni], afr[mi], bl);   // hi*lo
                }
            }
            // A-lo fragments (reuse regs), then lo*hi
#pragma unroll
            for (int mi = 0; mi < 4; mi++)
                ldsm4(afr[mi], buf + OF_ALO + rowA + mi * (16 * RB) + kb);
#pragma unroll
            for (int mi = 0; mi < 4; mi++) {
#pragma unroll
                for (int ni = 0; ni < 4; ni++) {
                    const int p = ni >> 1, s = ni & 1;
                    uint32_t bh[2] = {bhi[p][s], bhi[p][2 + s]};
                    mma16816(acc[mi][ni], afr[mi], bh);   // lo*hi
                }
            }
        }
        __syncthreads();
    }

    float2 bb[4];
#pragma unroll
    for (int ni = 0; ni < 4; ni++)
        bb[ni] = *reinterpret_cast<const float2*>(&bias[col0 + warpN * 32 + ni * 8 + tig * 2]);

#pragma unroll
    for (int mi = 0; mi < 4; mi++) {
        int rg = row0 + warpM * 64 + mi * 16 + group;
#pragma unroll
        for (int ni = 0; ni < 4; ni++) {
            int cg = col0 + warpN * 32 + ni * 8 + tig * 2;
            *reinterpret_cast<float2*>(&out[(size_t)rg * DIM + cg]) =
                make_float2(acc[mi][ni][0] + bb[ni].x, acc[mi][ni][1] + bb[ni].y);
            *reinterpret_cast<float2*>(&out[(size_t)(rg + 8) * DIM + cg]) =
                make_float2(acc[mi][ni][2] + bb[ni].x, acc[mi][ni][3] + bb[ni].y);
        }
    }
}

// =====================================================================================
// Kernel 2: rfft over head_dim (32 -> 17 complex bins) for ql and kl.
// =====================================================================================
__global__ __launch_bounds__(256) void rfft_heads()
{
    const int which = blockIdx.y;            // 0 -> Q, 1 -> K
    const float* __restrict__ src = g_lin[which];
    float2* __restrict__ dst = g_QK[which];

    __shared__ float xs[32 * 264];
    __shared__ float twc[32], tws[32];

    const int tid = threadIdx.x;
    if (tid < 32) {
        float s, c;
        sincospif((float)tid * (1.0f / 16.0f), &s, &c);
        twc[tid] = c; tws[tid] = s;
    }
    const int row0 = blockIdx.x * 32;
    for (int i = tid; i < 32 * 256; i += 256) {
        int tok = i >> 8, cc = i & 255;
        xs[tok * 264 + (cc >> 5) * 33 + (cc & 31)] = src[(size_t)row0 * DIM + i];
    }
    __syncthreads();

    const int tok = tid >> 3, h = tid & 7;
    float xr[32];
#pragma unroll
    for (int d = 0; d < 32; d++) xr[d] = xs[tok * 264 + h * 33 + d];

    const int b  = row0 >> 12;
    const int n  = (row0 & (SEQ - 1)) + tok;
    const int bh = b * HEADS + h;

    for (int f = 0; f < NFREQ; f++) {
        float re = 0.0f, im = 0.0f;
#pragma unroll
        for (int d = 0; d < 32; d++) {
            int k2 = (f * d) & 31;
            re = fmaf(xr[d], twc[k2], re);
            im = fmaf(xr[d], -tws[k2], im);
        }
        dst[((size_t)bh * NFREQ + f) * SEQ + n] = make_float2(re, im);
    }
}

// =====================================================================================
// Kernel 3: per (b,h,f) column: FFT4096(Q), FFT4096(K), pointwise mult (scaled),
// inverse FFT4096 -> g_P.  Radix-8 Stockham (4 stages), Qhat in registers.
// Skewed SMEM addressing SK(i)=i+(i>>3) kills the stage-0 16-way store conflicts.
// SMEM: tw(16KB) + 2 padded work buffers(2x36KB) = 88KB -> 2 CTAs/SM.
// =====================================================================================
#define SK(i) ((i) + ((i) >> 3))
#define FFT_BUF 4608          // SK(4095)=4606 -> 4608 float2 per work buffer

__device__ __forceinline__ float2 cmulf(float2 a, float2 b) {
    return make_float2(a.x * b.x - a.y * b.y, a.x * b.y + a.y * b.x);
}
// rot(v) = -i*v (fwd) / +i*v (inv)
template<bool INV>
__device__ __forceinline__ float2 rot90(float2 v) {
    return INV ? make_float2(-v.y, v.x) : make_float2(v.y, -v.x);
}
// w8mul(v) = W_8^1 * v  (W_8^1 = (c,-c) fwd, (c,c) inv), c = sqrt(2)/2
template<bool INV>
__device__ __forceinline__ float2 w8mul(float2 v) {
    const float c = 0.70710678118654752f;
    return INV ? make_float2(c * (v.x - v.y), c * (v.x + v.y))
               : make_float2(c * (v.x + v.y), c * (v.y - v.x));
}

template<bool INV>
__device__ __forceinline__ void fft8x(float2* __restrict__ xin, float2* __restrict__ yin,
                                      const float2* __restrict__ tw, int tid)
{
    float2* a = xin; float2* b = yin;
#pragma unroll 1
    for (int st = 0; st < 4; st++) {
        const int S = 1 << (3 * st);          // 1, 8, 64, 512
#pragma unroll
        for (int it = 0; it < 2; it++) {
            const int j  = tid + (it << 8);   // 0..511
            const int q  = j & (S - 1);
            const int pS = j - q;
            float2 x0 = a[SK(j)],        x1 = a[SK(j + 512)],  x2 = a[SK(j + 1024)], x3 = a[SK(j + 1536)];
            float2 x4 = a[SK(j + 2048)], x5 = a[SK(j + 2560)], x6 = a[SK(j + 3072)], x7 = a[SK(j + 3584)];
            // DFT8 via even/odd DFT4s (even: x0,x2,x4,x6 ; odd: x1,x3,x5,x7)
            float2 t0 = make_float2(x0.x + x4.x, x0.y + x4.y);
            float2 t1 = make_float2(x0.x - x4.x, x0.y - x4.y);
            float2 t2 = make_float2(x2.x + x6.x, x2.y + x6.y);
            float2 t3 = rot90<INV>(make_float2(x2.x - x6.x, x2.y - x6.y));
            float2 e0 = make_float2(t0.x + t2.x, t0.y + t2.y);
            float2 e2 = make_float2(t0.x - t2.x, t0.y - t2.y);
            float2 e1 = make_float2(t1.x + t3.x, t1.y + t3.y);
            float2 e3 = make_float2(t1.x - t3.x, t1.y - t3.y);
            float2 s0 = make_float2(x1.x + x5.x, x1.y + x5.y);
            float2 s1 = make_float2(x1.x - x5.x, x1.y - x5.y);
            float2 s2 = make_float2(x3.x + x7.x, x3.y + x7.y);
            float2 s3 = rot90<INV>(make_float2(x3.x - x7.x, x3.y - x7.y));
            float2 o0 = make_float2(s0.x + s2.x, s0.y + s2.y);
            float2 o2 = make_float2(s0.x - s2.x, s0.y - s2.y);
            float2 o1 = make_float2(s1.x + s3.x, s1.y + s3.y);
            float2 o3 = make_float2(s1.x - s3.x, s1.y - s3.y);
            // combine: u_m = W_8^m * o_m
            float2 u1 = w8mul<INV>(o1);
            float2 u2 = rot90<INV>(o2);
            float2 u3 = rot90<INV>(w8mul<INV>(o3));
            float2 X0 = make_float2(e0.x + o0.x, e0.y + o0.y);
            float2 X4 = make_float2(e0.x - o0.x, e0.y - o0.y);
            float2 X1 = make_float2(e1.x + u1.x, e1.y + u1.y);
            float2 X5 = make_float2(e1.x - u1.x, e1.y - u1.y);
            float2 X2 = make_float2(e2.x + u2.x, e2.y + u2.y);
            float2 X6 = make_float2(e2.x - u2.x, e2.y - u2.y);
            float2 X3 = make_float2(e3.x + u3.x, e3.y + u3.y);
            float2 X7 = make_float2(e3.x - u3.x, e3.y - u3.y);
            // twiddles W^{m*pS}: load w1,w2; chain the rest (conjugate for inverse)
            float2 w1 = tw[pS];
            float2 w2 = tw[2 * pS];
            if (INV) { w1.y = -w1.y; w2.y = -w2.y; }
            float2 w3 = cmulf(w2, w1);
            float2 w4 = cmulf(w2, w2);
            float2 w5 = cmulf(w4, w1);
            float2 w6 = cmulf(w4, w2);
            float2 w7 = cmulf(w4, w3);
            const int ob = 8 * pS + q;
            b[SK(ob)]         = X0;
            b[SK(ob + S)]     = cmulf(X1, w1);
            b[SK(ob + 2 * S)] = cmulf(X2, w2);
            b[SK(ob + 3 * S)] = cmulf(X3, w3);
            b[SK(ob + 4 * S)] = cmulf(X4, w4);
            b[SK(ob + 5 * S)] = cmulf(X5, w5);
            b[SK(ob + 6 * S)] = cmulf(X6, w6);
            b[SK(ob + 7 * S)] = cmulf(X7, w7);
        }
        __syncthreads();
        float2* tmp = a; a = b; b = tmp;
    }
    // 4 swaps -> result back in xin
}

__global__ __launch_bounds__(256) void fft_conv()
{
    extern __shared__ unsigned char smraw[];
    float2* tw = reinterpret_cast<float2*>(smraw);   // 2048
    float2* ba = tw + 2048;                          // FFT_BUF work A (skewed)
    float2* bb = ba + FFT_BUF;                       // FFT_BUF work B (skewed)

    const int tid = threadIdx.x;
    const int f   = blockIdx.x;      // 0..16
    const int bh  = blockIdx.y;      // 0..63
    const size_t base = ((size_t)bh * NFREQ + f) * SEQ;

    for (int i = tid; i < 2048; i += 256) {
        float s, c;
        sincospif((float)i * (1.0f / 2048.0f), &s, &c);
        tw[i] = make_float2(c, -s);
    }
#pragma unroll
    for (int r = 0; r < 16; r++) ba[SK(tid + 256 * r)] = g_QK[0][base + tid + 256 * r];
    __syncthreads();

    fft8x<false>(ba, bb, tw, tid);                   // Qhat in ba

    // stash Qhat in registers (thread owns indices tid + 256*r)
    float2 qreg[16];
#pragma unroll
    for (int r = 0; r < 16; r++) qreg[r] = ba[SK(tid + 256 * r)];
#pragma unroll
    for (int r = 0; r < 16; r++) ba[SK(tid + 256 * r)] = g_QK[1][base + tid + 256 * r];
    __syncthreads();

    fft8x<false>(ba, bb, tw, tid);                   // Khat in ba

    const float scale = 1.0f / 131072.0f;            // 1/(4096*32)
#pragma unroll
    for (int r = 0; r < 16; r++) {
        int i = SK(tid + 256 * r);
        float2 a = ba[i], q2 = qreg[r];
        ba[i] = make_float2((a.x * q2.x - a.y * q2.y) * scale,
                            (a.x * q2.y + a.y * q2.x) * scale);
    }
    __syncthreads();

    fft8x<true>(ba, bb, tw, tid);                    // inverse -> ba

#pragma unroll
    for (int r = 0; r < 16; r++) g_P[base + tid + 256 * r] = ba[SK(tid + 256 * r)];
}
#define FFT_SMEM ((2048 + 2 * FFT_BUF) * (int)sizeof(float2))   // 90112 B

// =====================================================================================
// Kernel 4: irfft-32 over heads + softmax(32) + value gate + residual + LayerNorm(256)
// Phase-batched: all 8 head-softmax reductions interleaved for SHFL latency hiding.
// =====================================================================================
__global__ __launch_bounds__(256) void epilogue(
    const float* __restrict__ vin, const float* __restrict__ gamma,
    const float* __restrict__ beta, float* __restrict__ out)
{
    __shared__ float2 Psm[HEADS * NFREQ * 32];   // [h][f][tok]
    __shared__ float c32[32], s32[32];

    const int tid = threadIdx.x;
    if (tid < 32) {
        float s, c;
        sincospif((float)tid * (1.0f / 16.0f), &s, &c);
        c32[tid] = c; s32[tid] = s;
    }
    const int row0 = blockIdx.x * 32;
    const int b = row0 >> 12, n0 = row0 & (SEQ - 1);

    for (int i = tid; i < HEADS * NFREQ * 32; i += 256) {
        int h = i / (NFREQ * 32);
        int r = i - h * (NFREQ * 32);
        int f = r >> 5, tok = r & 31;
        Psm[i] = g_P[(((size_t)(b * HEADS + h)) * NFREQ + f) * SEQ + n0 + tok];
    }
    __syncthreads();

    const int w = tid >> 5, d = tid & 31;
    const float* __restrict__ vl = g_lin[2];

    for (int it = 0; it < 4; it++) {
        const int tok = w + it * 8;
        const int row = row0 + tok;

        // phase 1: irfft-32 logits for all 8 heads
        float acc[8];
#pragma unroll
        for (int h = 0; h < 8; h++) {
            const float2* Ph = &Psm[h * NFREQ * 32 + tok];
            float a = Ph[0].x;                         // f = 0 (real)
            float2 F16 = Ph[16 * 32];
            a += (d & 1) ? -F16.x : F16.x;             // Nyquist (real)
#pragma unroll
            for (int f = 1; f <= 15; f++) {
                float2 F = Ph[f * 32];
                int k2 = (f * d) & 31;
                a += 2.0f * (F.x * c32[k2] - F.y * s32[k2]);
            }
            acc[h] = a;
        }

        // phase 2: batched max-reduction (8 independent chains interleaved)
        float m[8];
#pragma unroll
        for (int h = 0; h < 8; h++) m[h] = acc[h];
#pragma unroll
        for (int o = 16; o; o >>= 1)
#pragma unroll
            for (int h = 0; h < 8; h++)
                m[h] = fmaxf(m[h], __shfl_xor_sync(0xffffffffu, m[h], o));

        // phase 3: exp
        float e[8];
#pragma unroll
        for (int h = 0; h < 8; h++) e[h] = __expf(acc[h] - m[h]);

        // phase 4: batched sum-reduction
        float ss[8];
#pragma unroll
        for (int h = 0; h < 8; h++) ss[h] = e[h];
#pragma unroll
        for (int o = 16; o; o >>= 1)
#pragma unroll
            for (int h = 0; h < 8; h++)
                ss[h] += __shfl_xor_sync(0xffffffffu, ss[h], o);

        // phase 5: gate + residual; LN stats
        float gh[8];
        float s1 = 0.0f, s2 = 0.0f;
#pragma unroll
        for (int h = 0; h < 8; h++) {
            float p = __fdividef(e[h], ss[h]);
            int c = h * 32 + d;
            float vv = vl[(size_t)row * DIM + c];
            float rv = vin[(size_t)row * DIM + c];
            float g = fmaf(vv, p, rv);
            gh[h] = g; s1 += g; s2 = fmaf(g, g, s2);
        }
#pragma unroll
        for (int o = 16; o; o >>= 1) {
            s1 += __shfl_xor_sync(0xffffffffu, s1, o);
            s2 += __shfl_xor_sync(0xffffffffu, s2, o);
        }
        float mean = s1 * (1.0f / 256.0f);
        float var  = s2 * (1.0f / 256.0f) - mean * mean;
        float inv  = rsqrtf(var + 1e-5f);
#pragma unroll
        for (int h = 0; h < 8; h++) {
            int c = h * 32 + d;
            out[(size_t)row * DIM + c] = (gh[h] - mean) * inv * gamma[c] + beta[c];
        }
    }
}

// =====================================================================================
extern "C" void kernel_launch(void* const* d_in, const int* in_sizes, int n_in,
                              void* d_out, int out_size)
{
    const float* q     = (const float*)d_in[0];
    const float* k     = (const float*)d_in[1];
    const float* v     = (const float*)d_in[2];
    const float* Wq    = (const float*)d_in[3];
    const float* bq    = (const float*)d_in[4];
    const float* Wk    = (const float*)d_in[5];
    const float* bk    = (const float*)d_in[6];
    const float* Wv    = (const float*)d_in[7];
    const float* bv    = (const float*)d_in[8];
    const float* gamma = (const float*)d_in[9];
    const float* beta  = (const float*)d_in[10];
    float* out = (float*)d_out;

    cudaFuncSetAttribute(fft_conv, cudaFuncAttributeMaxDynamicSharedMemorySize, FFT_SMEM);
    cudaFuncSetAttribute(gemm_qkv_mma, cudaFuncAttributeMaxDynamicSharedMemorySize, SM_GEMM_TOTAL);

    convert_bf16<<<(NX4 + NW4 + 255) / 256, 256>>>(q, k, v, Wq, Wk, Wv);
    gemm_qkv_mma<<<dim3(ROWS / BM, DIM / BN, 3), 256, SM_GEMM_TOTAL>>>(bq, bk, bv);
    rfft_heads<<<dim3(ROWS / 32, 2), 256>>>();
    fft_conv<<<dim3(NFREQ, BH), 256, FFT_SMEM>>>();
    epilogue<<<ROWS / 32, 256>>>(v, gamma, beta, out);
}

// round 16
// speedup vs baseline: 1.8673x; 1.0916x over previous
#include <cuda_runtime.h>
#include <cuda_bf16.h>
#include <math_constants.h>
#include <cstdint>

// Problem constants
#define BATCH   8
#define SEQ     4096
#define DIM     256
#define HEADS   8
#define HD      32
#define NFREQ   17          // HD/2 + 1
#define ROWS    (BATCH*SEQ) // 32768
#define BH      (BATCH*HEADS) // 64

typedef unsigned long long u64;

// ---------------- scratch (static __device__ — no allocations allowed) ----------------
__device__ float  g_lin[3][(size_t)ROWS * DIM];            // ql, kl, vl
__device__ float2 g_QK[2][(size_t)BH * NFREQ * SEQ];       // Qhat, Khat
__device__ float2 g_P[(size_t)BH * NFREQ * SEQ];           // product after inverse seq-FFT
__device__ __nv_bfloat16 g_xhi[3][(size_t)ROWS * DIM];     // bf16 hi/lo split of q,k,v
__device__ __nv_bfloat16 g_xlo[3][(size_t)ROWS * DIM];
__device__ __nv_bfloat16 g_whi[3][DIM * DIM];              // and of Wq,Wk,Wv
__device__ __nv_bfloat16 g_wlo[3][DIM * DIM];

// ======================= small asm helpers ========================
__device__ __forceinline__ uint32_t smem_u32(const void* p) {
    uint32_t a;
    asm("{ .reg .u64 t; cvta.to.shared.u64 t, %1; cvt.u32.u64 %0, t; }" : "=r"(a) : "l"(p));
    return a;
}
__device__ __forceinline__ void cp16(uint32_t dst, const void* src) {
    asm volatile("cp.async.ca.shared.global [%0], [%1], 16;" :: "r"(dst), "l"(src));
}
__device__ __forceinline__ void cp_commit() { asm volatile("cp.async.commit_group;"); }
__device__ __forceinline__ void cp_wait0()  { asm volatile("cp.async.wait_group 0;"); }
__device__ __forceinline__ void ldsm4(uint32_t* r, uint32_t addr) {
    asm volatile("ldmatrix.sync.aligned.m8n8.x4.shared.b16 {%0,%1,%2,%3}, [%4];"
                 : "=r"(r[0]), "=r"(r[1]), "=r"(r[2]), "=r"(r[3]) : "r"(addr));
}
__device__ __forceinline__ void mma16816(float* c, const uint32_t* a, const uint32_t* b) {
    asm volatile(
        "mma.sync.aligned.m16n8k16.row.col.f32.bf16.bf16.f32 "
        "{%0,%1,%2,%3}, {%4,%5,%6,%7}, {%8,%9}, {%0,%1,%2,%3};"
        : "+f"(c[0]), "+f"(c[1]), "+f"(c[2]), "+f"(c[3])
        : "r"(a[0]), "r"(a[1]), "r"(a[2]), "r"(a[3]), "r"(b[0]), "r"(b[1]));
}
__device__ __forceinline__ void cvt_hi_lo(float4 xv, u64& hw, u64& lw) {
    __nv_bfloat16 h0 = __float2bfloat16_rn(xv.x);
    __nv_bfloat16 h1 = __float2bfloat16_rn(xv.y);
    __nv_bfloat16 h2 = __float2bfloat16_rn(xv.z);
    __nv_bfloat16 h3 = __float2bfloat16_rn(xv.w);
    __nv_bfloat16 l0 = __float2bfloat16_rn(xv.x - __bfloat162float(h0));
    __nv_bfloat16 l1 = __float2bfloat16_rn(xv.y - __bfloat162float(h1));
    __nv_bfloat16 l2 = __float2bfloat16_rn(xv.z - __bfloat162float(h2));
    __nv_bfloat16 l3 = __float2bfloat16_rn(xv.w - __bfloat162float(h3));
    hw = (u64)__bfloat16_as_ushort(h0) | ((u64)__bfloat16_as_ushort(h1) << 16)
       | ((u64)__bfloat16_as_ushort(h2) << 32) | ((u64)__bfloat16_as_ushort(h3) << 48);
    lw = (u64)__bfloat16_as_ushort(l0) | ((u64)__bfloat16_as_ushort(l1) << 16)
       | ((u64)__bfloat16_as_ushort(l2) << 32) | ((u64)__bfloat16_as_ushort(l3) << 48);
}

// =====================================================================================
// Kernel 0: fp32 -> bf16 hi/lo split for X (q,k,v) and W (Wq,Wk,Wv). Pure streaming.
// =====================================================================================
#define NX4 (3 * ROWS * DIM / 4)
#define NW4 (3 * DIM * DIM / 4)
__global__ __launch_bounds__(256) void convert_bf16(
    const float* __restrict__ q, const float* __restrict__ k, const float* __restrict__ v,
    const float* __restrict__ Wq, const float* __restrict__ Wk, const float* __restrict__ Wv)
{
    const int idx = blockIdx.x * 256 + threadIdx.x;
    u64 hw, lw;
    if (idx < NX4) {
        const int per = ROWS * DIM / 4;
        const int z = idx / per, off = idx - z * per;
        const float* src = (z == 0) ? q : (z == 1) ? k : v;
        cvt_hi_lo(reinterpret_cast<const float4*>(src)[off], hw, lw);
        reinterpret_cast<u64*>(g_xhi[z])[off] = hw;
        reinterpret_cast<u64*>(g_xlo[z])[off] = lw;
    } else if (idx < NX4 + NW4) {
        const int per = DIM * DIM / 4;
        const int iw = idx - NX4;
        const int z = iw / per, off = iw - z * per;
        const float* src = (z == 0) ? Wq : (z == 1) ? Wk : Wv;
        cvt_hi_lo(reinterpret_cast<const float4*>(src)[off], hw, lw);
        reinterpret_cast<u64*>(g_whi[z])[off] = hw;
        reinterpret_cast<u64*>(g_wlo[z])[off] = lw;
    }
}

// =====================================================================================
// Kernel 1: QKV GEMM on mma.sync, pre-split bf16 operands, cp.async double buffer,
// ldmatrix fragments. CTA: M=128 x N=128 (2 CTAs/SM). 8 warps = 2(M) x 4(N).
// =====================================================================================
#define BM 128
#define BN 128
#define BK 32
#define RB 80                 // bytes per SMEM row (40 bf16)
#define OF_AHI 0
#define OF_ALO (BM * RB)                   // 10240
#define OF_BHI (2 * BM * RB)               // 20480
#define OF_BLO (2 * BM * RB + BN * RB)     // 30720
#define BUF_SZ (2 * BM * RB + 2 * BN * RB) // 40960
#define SM_GEMM_TOTAL (2 * BUF_SZ)         // 81920

__device__ __forceinline__ void gemm_load_chunk(
    uint32_t buf, int tid, int kk, int row0, int col0,
    const __nv_bfloat16* Xhi, const __nv_bfloat16* Xlo,
    const __nv_bfloat16* Whi, const __nv_bfloat16* Wlo)
{
#pragma unroll
    for (int i = 0; i < 2; i++) {                 // A: 128 rows x 64B, hi + lo
        int idx = tid + 256 * i;
        int row = idx >> 2, j = idx & 3;
        size_t g = (size_t)(row0 + row) * DIM + kk + j * 8;
        uint32_t d = buf + row * RB + j * 16;
        cp16(d + OF_AHI, Xhi + g);
        cp16(d + OF_ALO, Xlo + g);
    }
#pragma unroll
    for (int i = 0; i < 2; i++) {                 // B: 128 rows x 64B, hi + lo
        int idx = tid + 256 * i;
        int row = idx >> 2, j = idx & 3;
        size_t g = (size_t)(col0 + row) * DIM + kk + j * 8;
        uint32_t d = buf + row * RB + j * 16;
        cp16(d + OF_BHI, Whi + g);
        cp16(d + OF_BLO, Wlo + g);
    }
}

__global__ __launch_bounds__(256, 2) void gemm_qkv_mma(
    const float* __restrict__ bq, const float* __restrict__ bk, const float* __restrict__ bv)
{
    extern __shared__ unsigned char smem[];
    const uint32_t sbase = smem_u32(smem);

    const int z = blockIdx.z;
    const __nv_bfloat16* Xhi = g_xhi[z];
    const __nv_bfloat16* Xlo = g_xlo[z];
    const __nv_bfloat16* Whi = g_whi[z];
    const __nv_bfloat16* Wlo = g_wlo[z];
    const float* bias = (z == 0) ? bq : (z == 1) ? bk : bv;
    float* out = g_lin[z];

    const int tid   = threadIdx.x;
    const int wid   = tid >> 5;
    const int lane  = tid & 31;
    const int group = lane >> 2;
    const int tig   = lane & 3;
    const int warpM = wid >> 2;       // 0..1 (x64 rows)
    const int warpN = wid & 3;        // 0..3 (x32 cols)
    const int row0  = blockIdx.x * BM;
    const int col0  = blockIdx.y * BN;

    const int tile = lane >> 3, ti = lane & 7;
    const uint32_t rowA = (uint32_t)(warpM * 64 + ((tile & 1) << 3) + ti) * RB;
    const uint32_t rowB = (uint32_t)(warpN * 32 + ((tile & 1) << 3) + ti) * RB;
    const uint32_t colT = (uint32_t)((tile >> 1) << 3) * 2;

    float acc[4][4][4];
#pragma unroll
    for (int mi = 0; mi < 4; mi++)
#pragma unroll
        for (int ni = 0; ni < 4; ni++)
#pragma unroll
            for (int r = 0; r < 4; r++) acc[mi][ni][r] = 0.0f;

    gemm_load_chunk(sbase, tid, 0, row0, col0, Xhi, Xlo, Whi, Wlo);
    cp_commit();

#pragma unroll 1
    for (int c = 0; c < DIM / BK; c++) {
        cp_wait0();
        __syncthreads();
        if (c + 1 < DIM / BK) {
            gemm_load_chunk(sbase + ((c + 1) & 1) * BUF_SZ, tid, (c + 1) * BK,
                            row0, col0, Xhi, Xlo, Whi, Wlo);
            cp_commit();
        }
        const uint32_t buf = sbase + (c & 1) * BUF_SZ;

#pragma unroll
        for (int ks = 0; ks < 2; ks++) {
            const uint32_t kb = (uint32_t)(ks * 32) + colT;
            uint32_t afr[4][4], bhi[2][4], blo[2][4];
#pragma unroll
            for (int p = 0; p < 2; p++) {
                ldsm4(bhi[p], buf + OF_BHI + rowB + p * (16 * RB) + kb);
                ldsm4(blo[p], buf + OF_BLO + rowB + p * (16 * RB) + kb);
            }
#pragma unroll
            for (int mi = 0; mi < 4; mi++)
                ldsm4(afr[mi], buf + OF_AHI + rowA + mi * (16 * RB) + kb);
#pragma unroll
            for (int mi = 0; mi < 4; mi++) {
#pragma unroll
                for (int ni = 0; ni < 4; ni++) {
                    const int p = ni >> 1, s = ni & 1;
                    uint32_t bh[2] = {bhi[p][s], bhi[p][2 + s]};
                    uint32_t bl[2] = {blo[p][s], blo[p][2 + s]};
                    mma16816(acc[mi][ni], afr[mi], bh);   // hi*hi
                    mma16816(acc[mi][ni], afr[mi], bl);   // hi*lo
                }
            }
#pragma unroll
            for (int mi = 0; mi < 4; mi++)
                ldsm4(afr[mi], buf + OF_ALO + rowA + mi * (16 * RB) + kb);
#pragma unroll
            for (int mi = 0; mi < 4; mi++) {
#pragma unroll
                for (int ni = 0; ni < 4; ni++) {
                    const int p = ni >> 1, s = ni & 1;
                    uint32_t bh[2] = {bhi[p][s], bhi[p][2 + s]};
                    mma16816(acc[mi][ni], afr[mi], bh);   // lo*hi
                }
            }
        }
        __syncthreads();
    }

    float2 bb[4];
#pragma unroll
    for (int ni = 0; ni < 4; ni++)
        bb[ni] = *reinterpret_cast<const float2*>(&bias[col0 + warpN * 32 + ni * 8 + tig * 2]);

#pragma unroll
    for (int mi = 0; mi < 4; mi++) {
        int rg = row0 + warpM * 64 + mi * 16 + group;
#pragma unroll
        for (int ni = 0; ni < 4; ni++) {
            int cg = col0 + warpN * 32 + ni * 8 + tig * 2;
            *reinterpret_cast<float2*>(&out[(size_t)rg * DIM + cg]) =
                make_float2(acc[mi][ni][0] + bb[ni].x, acc[mi][ni][1] + bb[ni].y);
            *reinterpret_cast<float2*>(&out[(size_t)(rg + 8) * DIM + cg]) =
                make_float2(acc[mi][ni][2] + bb[ni].x, acc[mi][ni][3] + bb[ni].y);
        }
    }
}

// =====================================================================================
// Kernel 2: rfft over head_dim (32 -> 17 complex bins) for ql and kl.
// =====================================================================================
__global__ __launch_bounds__(256) void rfft_heads()
{
    const int which = blockIdx.y;            // 0 -> Q, 1 -> K
    const float* __restrict__ src = g_lin[which];
    float2* __restrict__ dst = g_QK[which];

    __shared__ float xs[32 * 264];
    __shared__ float twc[32], tws[32];

    const int tid = threadIdx.x;
    if (tid < 32) {
        float s, c;
        sincospif((float)tid * (1.0f / 16.0f), &s, &c);
        twc[tid] = c; tws[tid] = s;
    }
    const int row0 = blockIdx.x * 32;
    for (int i = tid; i < 32 * 256; i += 256) {
        int tok = i >> 8, cc = i & 255;
        xs[tok * 264 + (cc >> 5) * 33 + (cc & 31)] = src[(size_t)row0 * DIM + i];
    }
    __syncthreads();

    const int tok = tid >> 3, h = tid & 7;
    float xr[32];
#pragma unroll
    for (int d = 0; d < 32; d++) xr[d] = xs[tok * 264 + h * 33 + d];

    const int b  = row0 >> 12;
    const int n  = (row0 & (SEQ - 1)) + tok;
    const int bh = b * HEADS + h;

    for (int f = 0; f < NFREQ; f++) {
        float re = 0.0f, im = 0.0f;
#pragma unroll
        for (int d = 0; d < 32; d++) {
            int k2 = (f * d) & 31;
            re = fmaf(xr[d], twc[k2], re);
            im = fmaf(xr[d], -tws[k2], im);
        }
        dst[((size_t)bh * NFREQ + f) * SEQ + n] = make_float2(re, im);
    }
}

// =====================================================================================
// Kernel 3: four-step register FFT, 4096 = 16*16*16.
// Three register DFT-16 stages, only two SMEM transposes (XOR-skewed, conflict-free).
// Qhat kept in registers; product done in permuted frequency layout (order-agnostic);
// inverse = exact mirrored pipeline. SMEM: 256-entry tw + 16x264 buffer = ~36KB static.
// =====================================================================================
__device__ __forceinline__ float2 cmulf(float2 a, float2 b) {
    return make_float2(a.x * b.x - a.y * b.y, a.x * b.y + a.y * b.x);
}
template<bool INV>
__device__ __forceinline__ float2 rot90(float2 v) {   // -i*v fwd, +i*v inv
    return INV ? make_float2(-v.y, v.x) : make_float2(v.y, -v.x);
}
template<bool INV>
__device__ __forceinline__ float2 cmulw(float2 z, float wr, float wi) {
    float wy = INV ? -wi : wi;
    return make_float2(z.x * wr - z.y * wy, z.x * wy + z.y * wr);
}
template<bool INV>
__device__ __forceinline__ void dft4(float2& x0, float2& x1, float2& x2, float2& x3) {
    float2 t0 = make_float2(x0.x + x2.x, x0.y + x2.y);
    float2 t1 = make_float2(x0.x - x2.x, x0.y - x2.y);
    float2 t2 = make_float2(x1.x + x3.x, x1.y + x3.y);
    float2 t3 = rot90<INV>(make_float2(x1.x - x3.x, x1.y - x3.y));
    x0 = make_float2(t0.x + t2.x, t0.y + t2.y);
    x1 = make_float2(t1.x + t3.x, t1.y + t3.y);
    x2 = make_float2(t0.x - t2.x, t0.y - t2.y);
    x3 = make_float2(t1.x - t3.x, t1.y - t3.y);
}
// 16-point DFT, natural order in AND out. out[k] = sum_n in[n] * W16^{±nk}.
template<bool INV>
__device__ __forceinline__ void dft16(float2* v) {
    // inner DFT4s over n1 (stride-4 subsequences); result c[n2][k1] at slot n2+4*k1
    dft4<INV>(v[0], v[4], v[8],  v[12]);
    dft4<INV>(v[1], v[5], v[9],  v[13]);
    dft4<INV>(v[2], v[6], v[10], v[14]);
    dft4<INV>(v[3], v[7], v[11], v[15]);
    // twiddle W16^{n2*k1}
    const float C1 = 0.92387953251128674f, S1 = 0.38268343236508978f, C2 = 0.70710678118654752f;
    v[5]  = cmulw<INV>(v[5],   C1, -S1);   // W^1
    v[6]  = cmulw<INV>(v[6],   C2, -C2);   // W^2
    v[7]  = cmulw<INV>(v[7],   S1, -C1);   // W^3
    v[9]  = cmulw<INV>(v[9],   C2, -C2);   // W^2
    v[10] = cmulw<INV>(v[10], 0.0f, -1.0f);// W^4
    v[11] = cmulw<INV>(v[11], -C2, -C2);   // W^6
    v[13] = cmulw<INV>(v[13],  S1, -C1);   // W^3
    v[14] = cmulw<INV>(v[14], -C2, -C2);   // W^6
    v[15] = cmulw<INV>(v[15], -C1,  S1);   // W^9
    // outer DFT4s over n2; X[k1+4k2] lands at slot 4k1+k2
    dft4<INV>(v[0],  v[1],  v[2],  v[3]);
    dft4<INV>(v[4],  v[5],  v[6],  v[7]);
    dft4<INV>(v[8],  v[9],  v[10], v[11]);
    dft4<INV>(v[12], v[13], v[14], v[15]);
    // permute to natural: out[k] = slot[((k&3)<<2) | (k>>2)]
    float2 t[16];
#pragma unroll
    for (int i = 0; i < 16; i++) t[i] = v[i];
#pragma unroll
    for (int k = 0; k < 16; k++) v[k] = t[((k & 3) << 2) | (k >> 2)];
}
// a[k] *= w^k, k=0..15 (w conjugated if INV)
template<bool INV>
__device__ __forceinline__ void twchain(float2* a, float2 w) {
    if (INV) w.y = -w.y;
    float2 acc = w;
#pragma unroll
    for (int k = 1; k < 16; k++) {
        a[k] = cmulf(a[k], acc);
        if (k < 15) acc = cmulf(acc, w);
    }
}

#define FROW 264   // transpose buffer row stride (float2); 264*2 mod 32 = 16 -> half-warp decorrelation

template<bool INV>
__device__ __forceinline__ void fft4096(float2* a, float2* buf, const float2* tw, int tid)
{
    const int k1g = tid >> 4, mj = tid & 15;
    const int rowb = k1g * FROW;
    if (!INV) {
        dft16<false>(a);                       // over n1 (thread = n2)
        twchain<false>(a, tw[tid]);            // W4096^{n2*k1}
#pragma unroll
        for (int k = 0; k < 16; k++) buf[k * FROW + tid] = a[k];       // T1 write
        __syncthreads();
#pragma unroll
        for (int m1 = 0; m1 < 16; m1++) a[m1] = buf[rowb + mj + 16 * m1]; // T1 read
        __syncthreads();
        dft16<false>(a);                       // over m1 (thread = (k1,m2))
        twchain<false>(a, tw[16 * mj]);        // W256^{m2*j1}
#pragma unroll
        for (int j1 = 0; j1 < 16; j1++) buf[rowb + j1 * 16 + (mj ^ j1)] = a[j1]; // T2 write
        __syncthreads();
#pragma unroll
        for (int m2 = 0; m2 < 16; m2++) a[m2] = buf[rowb + mj * 16 + (m2 ^ mj)]; // T2 read
        __syncthreads();
        dft16<false>(a);                       // over m2 -> X[k1 + 16*j1 + 256*j2] in a[j2]
    } else {
        dft16<true>(a);                        // invert S3c (over j2)
#pragma unroll
        for (int m2 = 0; m2 < 16; m2++) buf[rowb + mj * 16 + (m2 ^ mj)] = a[m2]; // T2^-1 write
        __syncthreads();
#pragma unroll
        for (int j1 = 0; j1 < 16; j1++) a[j1] = buf[rowb + j1 * 16 + (mj ^ j1)]; // T2^-1 read
        __syncthreads();
        twchain<true>(a, tw[16 * mj]);         // conj W256^{m2*j1}
        dft16<true>(a);                        // invert S3a (over j1)
#pragma unroll
        for (int m1 = 0; m1 < 16; m1++) buf[rowb + mj + 16 * m1] = a[m1];  // T1^-1 write
        __syncthreads();
#pragma unroll
        for (int k = 0; k < 16; k++) a[k] = buf[k * FROW + tid];           // T1^-1 read
        __syncthreads();
        twchain<true>(a, tw[tid]);             // conj W4096^{n2*k1}
        dft16<true>(a);                        // invert S1 -> x[tid + 256*n1] (unscaled)
    }
}

__global__ __launch_bounds__(256) void fft_conv()
{
    __shared__ float2 tw[256];
    __shared__ float2 buf[16 * FROW];          // 4224 float2 = 33.8KB

    const int tid = threadIdx.x;
    const int f   = blockIdx.x;      // 0..16
    const int bh  = blockIdx.y;      // 0..63
    const size_t base = ((size_t)bh * NFREQ + f) * SEQ;

    {
        float s, c;
        sincospif((float)tid * (1.0f / 2048.0f), &s, &c);
        tw[tid] = make_float2(c, -s);          // W_4096^tid
    }
    float2 a[16];
#pragma unroll
    for (int r = 0; r < 16; r++) a[r] = g_QK[0][base + tid + 256 * r];
    __syncthreads();

    fft4096<false>(a, buf, tw, tid);           // Qhat (permuted layout, in regs)
    float2 qreg[16];
#pragma unroll
    for (int r = 0; r < 16; r++) qreg[r] = a[r];
#pragma unroll
    for (int r = 0; r < 16; r++) a[r] = g_QK[1][base + tid + 256 * r];

    fft4096<false>(a, buf, tw, tid);           // Khat (same layout)

    const float scale = 1.0f / 131072.0f;      // 1/(4096 * 32)
#pragma unroll
    for (int r = 0; r < 16; r++) {
        float2 kv = a[r], qv = qreg[r];
        a[r] = make_float2((kv.x * qv.x - kv.y * qv.y) * scale,
                           (kv.x * qv.y + kv.y * qv.x) * scale);
    }

    fft4096<true>(a, buf, tw, tid);            // inverse -> natural layout

#pragma unroll
    for (int r = 0; r < 16; r++) g_P[base + tid + 256 * r] = a[r];
}

// =====================================================================================
// Kernel 4: irfft-32 over heads + softmax(32) + value gate + residual + LayerNorm(256)
// Phase-batched: all 8 head-softmax reductions interleaved for SHFL latency hiding.
// =====================================================================================
__global__ __launch_bounds__(256) void epilogue(
    const float* __restrict__ vin, const float* __restrict__ gamma,
    const float* __restrict__ beta, float* __restrict__ out)
{
    __shared__ float2 Psm[HEADS * NFREQ * 32];   // [h][f][tok]
    __shared__ float c32[32], s32[32];

    const int tid = threadIdx.x;
    if (tid < 32) {
        float s, c;
        sincospif((float)tid * (1.0f / 16.0f), &s, &c);
        c32[tid] = c; s32[tid] = s;
    }
    const int row0 = blockIdx.x * 32;
    const int b = row0 >> 12, n0 = row0 & (SEQ - 1);

    for (int i = tid; i < HEADS * NFREQ * 32; i += 256) {
        int h = i / (NFREQ * 32);
        int r = i - h * (NFREQ * 32);
        int f = r >> 5, tok = r & 31;
        Psm[i] = g_P[(((size_t)(b * HEADS + h)) * NFREQ + f) * SEQ + n0 + tok];
    }
    __syncthreads();

    const int w = tid >> 5, d = tid & 31;
    const float* __restrict__ vl = g_lin[2];

    for (int it = 0; it < 4; it++) {
        const int tok = w + it * 8;
        const int row = row0 + tok;

        // phase 1: irfft-32 logits for all 8 heads
        float acc[8];
#pragma unroll
        for (int h = 0; h < 8; h++) {
            const float2* Ph = &Psm[h * NFREQ * 32 + tok];
            float a = Ph[0].x;                         // f = 0 (real)
            float2 F16 = Ph[16 * 32];
            a += (d & 1) ? -F16.x : F16.x;             // Nyquist (real)
#pragma unroll
            for (int f = 1; f <= 15; f++) {
                float2 F = Ph[f * 32];
                int k2 = (f * d) & 31;
                a += 2.0f * (F.x * c32[k2] - F.y * s32[k2]);
            }
            acc[h] = a;
        }

        // phase 2: batched max-reduction
        float m[8];
#pragma unroll
        for (int h = 0; h < 8; h++) m[h] = acc[h];
#pragma unroll
        for (int o = 16; o; o >>= 1)
#pragma unroll
            for (int h = 0; h < 8; h++)
                m[h] = fmaxf(m[h], __shfl_xor_sync(0xffffffffu, m[h], o));

        // phase 3: exp
        float e[8];
#pragma unroll
        for (int h = 0; h < 8; h++) e[h] = __expf(acc[h] - m[h]);

        // phase 4: batched sum-reduction
        float ss[8];
#pragma unroll
        for (int h = 0; h < 8; h++) ss[h] = e[h];
#pragma unroll
        for (int o = 16; o; o >>= 1)
#pragma unroll
            for (int h = 0; h < 8; h++)
                ss[h] += __shfl_xor_sync(0xffffffffu, ss[h], o);

        // phase 5: gate + residual; LN stats
        float gh[8];
        float s1 = 0.0f, s2 = 0.0f;
#pragma unroll
        for (int h = 0; h < 8; h++) {
            float p = __fdividef(e[h], ss[h]);
            int c = h * 32 + d;
            float vv = vl[(size_t)row * DIM + c];
            float rv = vin[(size_t)row * DIM + c];
            float g = fmaf(vv, p, rv);
            gh[h] = g; s1 += g; s2 = fmaf(g, g, s2);
        }
#pragma unroll
        for (int o = 16; o; o >>= 1) {
            s1 += __shfl_xor_sync(0xffffffffu, s1, o);
            s2 += __shfl_xor_sync(0xffffffffu, s2, o);
        }
        float mean = s1 * (1.0f / 256.0f);
        float var  = s2 * (1.0f / 256.0f) - mean * mean;
        float inv  = rsqrtf(var + 1e-5f);
#pragma unroll
        for (int h = 0; h < 8; h++) {
            int c = h * 32 + d;
            out[(size_t)row * DIM + c] = (gh[h] - mean) * inv * gamma[c] + beta[c];
        }
    }
}

// =====================================================================================
extern "C" void kernel_launch(void* const* d_in, const int* in_sizes, int n_in,
                              void* d_out, int out_size)
{
    const float* q     = (const float*)d_in[0];
    const float* k     = (const float*)d_in[1];
    const float* v     = (const float*)d_in[2];
    const float* Wq    = (const float*)d_in[3];
    const float* bq    = (const float*)d_in[4];
    const float* Wk    = (const float*)d_in[5];
    const float* bk    = (const float*)d_in[6];
    const float* Wv    = (const float*)d_in[7];
    const float* bv    = (const float*)d_in[8];
    const float* gamma = (const float*)d_in[9];
    const float* beta  = (const float*)d_in[10];
    float* out = (float*)d_out;

    cudaFuncSetAttribute(gemm_qkv_mma, cudaFuncAttributeMaxDynamicSharedMemorySize, SM_GEMM_TOTAL);

    convert_bf16<<<(NX4 + NW4 + 255) / 256, 256>>>(q, k, v, Wq, Wk, Wv);
    gemm_qkv_mma<<<dim3(ROWS / BM, DIM / BN, 3), 256, SM_GEMM_TOTAL>>>(bq, bk, bv);
    rfft_heads<<<dim3(ROWS / 32, 2), 256>>>();
    fft_conv<<<dim3(NFREQ, BH), 256>>>();
    epilogue<<<ROWS / 32, 256>>>(v, gamma, beta, out);
}

// round 17
// speedup vs baseline: 2.0128x; 1.0779x over previous
#include <cuda_runtime.h>
#include <cuda_bf16.h>
#include <math_constants.h>
#include <cstdint>

// Problem constants
#define BATCH   8
#define SEQ     4096
#define DIM     256
#define HEADS   8
#define HD      32
#define NFREQ   17          // HD/2 + 1
#define ROWS    (BATCH*SEQ) // 32768
#define BH      (BATCH*HEADS) // 64

typedef unsigned long long u64;

// ---------------- scratch (static __device__ — no allocations allowed) ----------------
__device__ float  g_lin[3][(size_t)ROWS * DIM];            // vl (only z=2 used now)
__device__ float2 g_QK[2][(size_t)BH * NFREQ * SEQ];       // Qhat, Khat
__device__ float2 g_P[(size_t)BH * NFREQ * SEQ];           // product after inverse seq-FFT
__device__ __nv_bfloat16 g_xhi[3][(size_t)ROWS * DIM];     // bf16 hi/lo split of q,k,v
__device__ __nv_bfloat16 g_xlo[3][(size_t)ROWS * DIM];
__device__ __nv_bfloat16 g_whi[3][DIM * DIM];              // and of Wq,Wk,Wv
__device__ __nv_bfloat16 g_wlo[3][DIM * DIM];

// ======================= small asm helpers ========================
__device__ __forceinline__ uint32_t smem_u32(const void* p) {
    uint32_t a;
    asm("{ .reg .u64 t; cvta.to.shared.u64 t, %1; cvt.u32.u64 %0, t; }" : "=r"(a) : "l"(p));
    return a;
}
__device__ __forceinline__ void cp16(uint32_t dst, const void* src) {
    asm volatile("cp.async.ca.shared.global [%0], [%1], 16;" :: "r"(dst), "l"(src));
}
__device__ __forceinline__ void cp_commit() { asm volatile("cp.async.commit_group;"); }
__device__ __forceinline__ void cp_wait0()  { asm volatile("cp.async.wait_group 0;"); }
__device__ __forceinline__ void ldsm4(uint32_t* r, uint32_t addr) {
    asm volatile("ldmatrix.sync.aligned.m8n8.x4.shared.b16 {%0,%1,%2,%3}, [%4];"
                 : "=r"(r[0]), "=r"(r[1]), "=r"(r[2]), "=r"(r[3]) : "r"(addr));
}
__device__ __forceinline__ void mma16816(float* c, const uint32_t* a, const uint32_t* b) {
    asm volatile(
        "mma.sync.aligned.m16n8k16.row.col.f32.bf16.bf16.f32 "
        "{%0,%1,%2,%3}, {%4,%5,%6,%7}, {%8,%9}, {%0,%1,%2,%3};"
        : "+f"(c[0]), "+f"(c[1]), "+f"(c[2]), "+f"(c[3])
        : "r"(a[0]), "r"(a[1]), "r"(a[2]), "r"(a[3]), "r"(b[0]), "r"(b[1]));
}
__device__ __forceinline__ void cvt_hi_lo(float4 xv, u64& hw, u64& lw) {
    __nv_bfloat16 h0 = __float2bfloat16_rn(xv.x);
    __nv_bfloat16 h1 = __float2bfloat16_rn(xv.y);
    __nv_bfloat16 h2 = __float2bfloat16_rn(xv.z);
    __nv_bfloat16 h3 = __float2bfloat16_rn(xv.w);
    __nv_bfloat16 l0 = __float2bfloat16_rn(xv.x - __bfloat162float(h0));
    __nv_bfloat16 l1 = __float2bfloat16_rn(xv.y - __bfloat162float(h1));
    __nv_bfloat16 l2 = __float2bfloat16_rn(xv.z - __bfloat162float(h2));
    __nv_bfloat16 l3 = __float2bfloat16_rn(xv.w - __bfloat162float(h3));
    hw = (u64)__bfloat16_as_ushort(h0) | ((u64)__bfloat16_as_ushort(h1) << 16)
       | ((u64)__bfloat16_as_ushort(h2) << 32) | ((u64)__bfloat16_as_ushort(h3) << 48);
    lw = (u64)__bfloat16_as_ushort(l0) | ((u64)__bfloat16_as_ushort(l1) << 16)
       | ((u64)__bfloat16_as_ushort(l2) << 32) | ((u64)__bfloat16_as_ushort(l3) << 48);
}

// =====================================================================================
// Kernel 0: fp32 -> bf16 hi/lo split for X (q,k,v) and W (Wq,Wk,Wv). Pure streaming.
// =====================================================================================
#define NX4 (3 * ROWS * DIM / 4)
#define NW4 (3 * DIM * DIM / 4)
__global__ __launch_bounds__(256) void convert_bf16(
    const float* __restrict__ q, const float* __restrict__ k, const float* __restrict__ v,
    const float* __restrict__ Wq, const float* __restrict__ Wk, const float* __restrict__ Wv)
{
    const int idx = blockIdx.x * 256 + threadIdx.x;
    u64 hw, lw;
    if (idx < NX4) {
        const int per = ROWS * DIM / 4;
        const int z = idx / per, off = idx - z * per;
        const float* src = (z == 0) ? q : (z == 1) ? k : v;
        cvt_hi_lo(reinterpret_cast<const float4*>(src)[off], hw, lw);
        reinterpret_cast<u64*>(g_xhi[z])[off] = hw;
        reinterpret_cast<u64*>(g_xlo[z])[off] = lw;
    } else if (idx < NX4 + NW4) {
        const int per = DIM * DIM / 4;
        const int iw = idx - NX4;
        const int z = iw / per, off = iw - z * per;
        const float* src = (z == 0) ? Wq : (z == 1) ? Wk : Wv;
        cvt_hi_lo(reinterpret_cast<const float4*>(src)[off], hw, lw);
        reinterpret_cast<u64*>(g_whi[z])[off] = hw;
        reinterpret_cast<u64*>(g_wlo[z])[off] = lw;
    }
}

// =====================================================================================
// Kernel 1: QKV GEMM on mma.sync (pre-split bf16, cp.async double buffer, ldmatrix).
// CTA: M=128 x N=128 (2 CTAs/SM), 8 warps = 2(M) x 4(N).
// For z in {Q,K}: head-rfft (DFT-32 over head_dim) FUSED into the epilogue — the
// N-block holds exactly 4 heads; tile is staged in SMEM and g_QK written directly.
// For z == V: plain bias+store to g_lin[2].
// =====================================================================================
#define BM 128
#define BN 128
#define BK 32
#define RB 80                 // bytes per SMEM row (40 bf16)
#define OF_AHI 0
#define OF_ALO (BM * RB)                   // 10240
#define OF_BHI (2 * BM * RB)               // 20480
#define OF_BLO (2 * BM * RB + BN * RB)     // 30720
#define BUF_SZ (2 * BM * RB + 2 * BN * RB) // 40960
#define SM_GEMM_TOTAL (2 * BUF_SZ)         // 81920 (also reused as 128x133 fp32 stage)

__device__ __forceinline__ void gemm_load_chunk(
    uint32_t buf, int tid, int kk, int row0, int col0,
    const __nv_bfloat16* Xhi, const __nv_bfloat16* Xlo,
    const __nv_bfloat16* Whi, const __nv_bfloat16* Wlo)
{
#pragma unroll
    for (int i = 0; i < 2; i++) {                 // A: 128 rows x 64B, hi + lo
        int idx = tid + 256 * i;
        int row = idx >> 2, j = idx & 3;
        size_t g = (size_t)(row0 + row) * DIM + kk + j * 8;
        uint32_t d = buf + row * RB + j * 16;
        cp16(d + OF_AHI, Xhi + g);
        cp16(d + OF_ALO, Xlo + g);
    }
#pragma unroll
    for (int i = 0; i < 2; i++) {                 // B: 128 rows x 64B, hi + lo
        int idx = tid + 256 * i;
        int row = idx >> 2, j = idx & 3;
        size_t g = (size_t)(col0 + row) * DIM + kk + j * 8;
        uint32_t d = buf + row * RB + j * 16;
        cp16(d + OF_BHI, Whi + g);
        cp16(d + OF_BLO, Wlo + g);
    }
}

__global__ __launch_bounds__(256, 2) void gemm_qkv_mma(
    const float* __restrict__ bq, const float* __restrict__ bk, const float* __restrict__ bv)
{
    extern __shared__ unsigned char smem[];
    const uint32_t sbase = smem_u32(smem);
    __shared__ float twc32[32], tws32[32];

    const int z = blockIdx.z;
    const __nv_bfloat16* Xhi = g_xhi[z];
    const __nv_bfloat16* Xlo = g_xlo[z];
    const __nv_bfloat16* Whi = g_whi[z];
    const __nv_bfloat16* Wlo = g_wlo[z];
    const float* bias = (z == 0) ? bq : (z == 1) ? bk : bv;

    const int tid   = threadIdx.x;
    const int wid   = tid >> 5;
    const int lane  = tid & 31;
    const int group = lane >> 2;
    const int tig   = lane & 3;
    const int warpM = wid >> 2;       // 0..1 (x64 rows)
    const int warpN = wid & 3;        // 0..3 (x32 cols) == local head for z<2
    const int row0  = blockIdx.x * BM;
    const int col0  = blockIdx.y * BN;

    if (tid < 32) {
        float s, c;
        sincospif((float)tid * (1.0f / 16.0f), &s, &c);
        twc32[tid] = c; tws32[tid] = s;
    }

    const int tile = lane >> 3, ti = lane & 7;
    const uint32_t rowA = (uint32_t)(warpM * 64 + ((tile & 1) << 3) + ti) * RB;
    const uint32_t rowB = (uint32_t)(warpN * 32 + ((tile & 1) << 3) + ti) * RB;
    const uint32_t colT = (uint32_t)((tile >> 1) << 3) * 2;

    float acc[4][4][4];
#pragma unroll
    for (int mi = 0; mi < 4; mi++)
#pragma unroll
        for (int ni = 0; ni < 4; ni++)
#pragma unroll
            for (int r = 0; r < 4; r++) acc[mi][ni][r] = 0.0f;

    gemm_load_chunk(sbase, tid, 0, row0, col0, Xhi, Xlo, Whi, Wlo);
    cp_commit();

#pragma unroll 1
    for (int c = 0; c < DIM / BK; c++) {
        cp_wait0();
        __syncthreads();
        if (c + 1 < DIM / BK) {
            gemm_load_chunk(sbase + ((c + 1) & 1) * BUF_SZ, tid, (c + 1) * BK,
                            row0, col0, Xhi, Xlo, Whi, Wlo);
            cp_commit();
        }
        const uint32_t buf = sbase + (c & 1) * BUF_SZ;

#pragma unroll
        for (int ks = 0; ks < 2; ks++) {
            const uint32_t kb = (uint32_t)(ks * 32) + colT;
            uint32_t afr[4][4], bhi[2][4], blo[2][4];
#pragma unroll
            for (int p = 0; p < 2; p++) {
                ldsm4(bhi[p], buf + OF_BHI + rowB + p * (16 * RB) + kb);
                ldsm4(blo[p], buf + OF_BLO + rowB + p * (16 * RB) + kb);
            }
#pragma unroll
            for (int mi = 0; mi < 4; mi++)
                ldsm4(afr[mi], buf + OF_AHI + rowA + mi * (16 * RB) + kb);
#pragma unroll
            for (int mi = 0; mi < 4; mi++) {
#pragma unroll
                for (int ni = 0; ni < 4; ni++) {
                    const int p = ni >> 1, s = ni & 1;
                    uint32_t bh[2] = {bhi[p][s], bhi[p][2 + s]};
                    uint32_t bl[2] = {blo[p][s], blo[p][2 + s]};
                    mma16816(acc[mi][ni], afr[mi], bh);   // hi*hi
                    mma16816(acc[mi][ni], afr[mi], bl);   // hi*lo
                }
            }
#pragma unroll
            for (int mi = 0; mi < 4; mi++)
                ldsm4(afr[mi], buf + OF_ALO + rowA + mi * (16 * RB) + kb);
#pragma unroll
            for (int mi = 0; mi < 4; mi++) {
#pragma unroll
                for (int ni = 0; ni < 4; ni++) {
                    const int p = ni >> 1, s = ni & 1;
                    uint32_t bh[2] = {bhi[p][s], bhi[p][2 + s]};
                    mma16816(acc[mi][ni], afr[mi], bh);   // lo*hi
                }
            }
        }
        __syncthreads();
    }

    float2 bb[4];
#pragma unroll
    for (int ni = 0; ni < 4; ni++)
        bb[ni] = *reinterpret_cast<const float2*>(&bias[col0 + warpN * 32 + ni * 8 + tig * 2]);

    if (z == 2) {
        // V: bias + store to g_lin[2]
        float* out = g_lin[2];
#pragma unroll
        for (int mi = 0; mi < 4; mi++) {
            int rg = row0 + warpM * 64 + mi * 16 + group;
#pragma unroll
            for (int ni = 0; ni < 4; ni++) {
                int cg = col0 + warpN * 32 + ni * 8 + tig * 2;
                *reinterpret_cast<float2*>(&out[(size_t)rg * DIM + cg]) =
                    make_float2(acc[mi][ni][0] + bb[ni].x, acc[mi][ni][1] + bb[ni].y);
                *reinterpret_cast<float2*>(&out[(size_t)(rg + 8) * DIM + cg]) =
                    make_float2(acc[mi][ni][2] + bb[ni].x, acc[mi][ni][3] + bb[ni].y);
            }
        }
    } else {
        // Q/K: stage tile (bias added) then fused head-rfft -> g_QK
        float* stage = reinterpret_cast<float*>(smem);   // 128 rows x 133 floats (68KB < 80KB)
#pragma unroll
        for (int mi = 0; mi < 4; mi++) {
            int rl = warpM * 64 + mi * 16 + group;
#pragma unroll
            for (int ni = 0; ni < 4; ni++) {
                int co = warpN * 33 + ni * 8 + tig * 2;    // head offset 33, 128 data cols
                stage[rl * 133 + co]           = acc[mi][ni][0] + bb[ni].x;
                stage[rl * 133 + co + 1]       = acc[mi][ni][1] + bb[ni].y;
                stage[(rl + 8) * 133 + co]     = acc[mi][ni][2] + bb[ni].x;
                stage[(rl + 8) * 133 + co + 1] = acc[mi][ni][3] + bb[ni].y;
            }
        }
        __syncthreads();

        float2* dst = g_QK[z];
        const int row  = tid >> 1;
        const int grow = row0 + row;
        const int b    = grow >> 12;
        const int n    = grow & (SEQ - 1);
#pragma unroll
        for (int hh = 0; hh < 2; hh++) {
            const int h = (tid & 1) * 2 + hh;
            float xr[32];
#pragma unroll
            for (int d = 0; d < 32; d++) xr[d] = stage[row * 133 + h * 33 + d];
            const int hglob = blockIdx.y * 4 + h;
            const size_t basep = (size_t)(b * HEADS + hglob) * NFREQ * SEQ + n;
#pragma unroll 1
            for (int f = 0; f < NFREQ; f++) {
                float re = 0.0f, im = 0.0f;
#pragma unroll
                for (int d = 0; d < 32; d++) {
                    int k2 = (f * d) & 31;
                    re = fmaf(xr[d], twc32[k2], re);
                    im = fmaf(xr[d], -tws32[k2], im);
                }
                dst[basep + (size_t)f * SEQ] = make_float2(re, im);
            }
        }
    }
}

// =====================================================================================
// Kernel 3: four-step register FFT, 4096 = 16*16*16 (unchanged from round 16).
// =====================================================================================
__device__ __forceinline__ float2 cmulf(float2 a, float2 b) {
    return make_float2(a.x * b.x - a.y * b.y, a.x * b.y + a.y * b.x);
}
template<bool INV>
__device__ __forceinline__ float2 rot90(float2 v) {   // -i*v fwd, +i*v inv
    return INV ? make_float2(-v.y, v.x) : make_float2(v.y, -v.x);
}
template<bool INV>
__device__ __forceinline__ float2 cmulw(float2 z, float wr, float wi) {
    float wy = INV ? -wi : wi;
    return make_float2(z.x * wr - z.y * wy, z.x * wy + z.y * wr);
}
template<bool INV>
__device__ __forceinline__ void dft4(float2& x0, float2& x1, float2& x2, float2& x3) {
    float2 t0 = make_float2(x0.x + x2.x, x0.y + x2.y);
    float2 t1 = make_float2(x0.x - x2.x, x0.y - x2.y);
    float2 t2 = make_float2(x1.x + x3.x, x1.y + x3.y);
    float2 t3 = rot90<INV>(make_float2(x1.x - x3.x, x1.y - x3.y));
    x0 = make_float2(t0.x + t2.x, t0.y + t2.y);
    x1 = make_float2(t1.x + t3.x, t1.y + t3.y);
    x2 = make_float2(t0.x - t2.x, t0.y - t2.y);
    x3 = make_float2(t1.x - t3.x, t1.y - t3.y);
}
template<bool INV>
__device__ __forceinline__ void dft16(float2* v) {
    dft4<INV>(v[0], v[4], v[8],  v[12]);
    dft4<INV>(v[1], v[5], v[9],  v[13]);
    dft4<INV>(v[2], v[6], v[10], v[14]);
    dft4<INV>(v[3], v[7], v[11], v[15]);
    const float C1 = 0.92387953251128674f, S1 = 0.38268343236508978f, C2 = 0.70710678118654752f;
    v[5]  = cmulw<INV>(v[5],   C1, -S1);
    v[6]  = cmulw<INV>(v[6],   C2, -C2);
    v[7]  = cmulw<INV>(v[7],   S1, -C1);
    v[9]  = cmulw<INV>(v[9],   C2, -C2);
    v[10] = cmulw<INV>(v[10], 0.0f, -1.0f);
    v[11] = cmulw<INV>(v[11], -C2, -C2);
    v[13] = cmulw<INV>(v[13],  S1, -C1);
    v[14] = cmulw<INV>(v[14], -C2, -C2);
    v[15] = cmulw<INV>(v[15], -C1,  S1);
    dft4<INV>(v[0],  v[1],  v[2],  v[3]);
    dft4<INV>(v[4],  v[5],  v[6],  v[7]);
    dft4<INV>(v[8],  v[9],  v[10], v[11]);
    dft4<INV>(v[12], v[13], v[14], v[15]);
    float2 t[16];
#pragma unroll
    for (int i = 0; i < 16; i++) t[i] = v[i];
#pragma unroll
    for (int k = 0; k < 16; k++) v[k] = t[((k & 3) << 2) | (k >> 2)];
}
template<bool INV>
__device__ __forceinline__ void twchain(float2* a, float2 w) {
    if (INV) w.y = -w.y;
    float2 acc = w;
#pragma unroll
    for (int k = 1; k < 16; k++) {
        a[k] = cmulf(a[k], acc);
        if (k < 15) acc = cmulf(acc, w);
    }
}

#define FROW 264

template<bool INV>
__device__ __forceinline__ void fft4096(float2* a, float2* buf, const float2* tw, int tid)
{
    const int k1g = tid >> 4, mj = tid & 15;
    const int rowb = k1g * FROW;
    if (!INV) {
        dft16<false>(a);
        twchain<false>(a, tw[tid]);
#pragma unroll
        for (int k = 0; k < 16; k++) buf[k * FROW + tid] = a[k];
        __syncthreads();
#pragma unroll
        for (int m1 = 0; m1 < 16; m1++) a[m1] = buf[rowb + mj + 16 * m1];
        __syncthreads();
        dft16<false>(a);
        twchain<false>(a, tw[16 * mj]);
#pragma unroll
        for (int j1 = 0; j1 < 16; j1++) buf[rowb + j1 * 16 + (mj ^ j1)] = a[j1];
        __syncthreads();
#pragma unroll
        for (int m2 = 0; m2 < 16; m2++) a[m2] = buf[rowb + mj * 16 + (m2 ^ mj)];
        __syncthreads();
        dft16<false>(a);
    } else {
        dft16<true>(a);
#pragma unroll
        for (int m2 = 0; m2 < 16; m2++) buf[rowb + mj * 16 + (m2 ^ mj)] = a[m2];
        __syncthreads();
#pragma unroll
        for (int j1 = 0; j1 < 16; j1++) a[j1] = buf[rowb + j1 * 16 + (mj ^ j1)];
        __syncthreads();
        twchain<true>(a, tw[16 * mj]);
        dft16<true>(a);
#pragma unroll
        for (int m1 = 0; m1 < 16; m1++) buf[rowb + mj + 16 * m1] = a[m1];
        __syncthreads();
#pragma unroll
        for (int k = 0; k < 16; k++) a[k] = buf[k * FROW + tid];
        __syncthreads();
        twchain<true>(a, tw[tid]);
        dft16<true>(a);
    }
}

__global__ __launch_bounds__(256) void fft_conv()
{
    __shared__ float2 tw[256];
    __shared__ float2 buf[16 * FROW];

    const int tid = threadIdx.x;
    const int f   = blockIdx.x;      // 0..16
    const int bh  = blockIdx.y;      // 0..63
    const size_t base = ((size_t)bh * NFREQ + f) * SEQ;

    {
        float s, c;
        sincospif((float)tid * (1.0f / 2048.0f), &s, &c);
        tw[tid] = make_float2(c, -s);
    }
    float2 a[16];
#pragma unroll
    for (int r = 0; r < 16; r++) a[r] = g_QK[0][base + tid + 256 * r];
    __syncthreads();

    fft4096<false>(a, buf, tw, tid);
    float2 qreg[16];
#pragma unroll
    for (int r = 0; r < 16; r++) qreg[r] = a[r];
#pragma unroll
    for (int r = 0; r < 16; r++) a[r] = g_QK[1][base + tid + 256 * r];

    fft4096<false>(a, buf, tw, tid);

    const float scale = 1.0f / 131072.0f;      // 1/(4096 * 32)
#pragma unroll
    for (int r = 0; r < 16; r++) {
        float2 kv = a[r], qv = qreg[r];
        a[r] = make_float2((kv.x * qv.x - kv.y * qv.y) * scale,
                           (kv.x * qv.y + kv.y * qv.x) * scale);
    }

    fft4096<true>(a, buf, tw, tid);

#pragma unroll
    for (int r = 0; r < 16; r++) g_P[base + tid + 256 * r] = a[r];
}

// =====================================================================================
// Kernel 4: irfft-32 + softmax + gate + residual + LayerNorm.
// Psm layout [tok][h][f] (stride 18, head rows 16B-aligned) -> vectorized f-loads.
// =====================================================================================
__global__ __launch_bounds__(256) void epilogue(
    const float* __restrict__ vin, const float* __restrict__ gamma,
    const float* __restrict__ beta, float* __restrict__ out)
{
    __shared__ float2 Psm[32 * 8 * 18];          // [tok][h][f], 36864B
    __shared__ float c32[32], s32[32];

    const int tid = threadIdx.x;
    if (tid < 32) {
        float s, c;
        sincospif((float)tid * (1.0f / 16.0f), &s, &c);
        c32[tid] = c; s32[tid] = s;
    }
    const int row0 = blockIdx.x * 32;
    const int b = row0 >> 12, n0 = row0 & (SEQ - 1);

    for (int i = tid; i < 32 * 8 * NFREQ; i += 256) {
        int tok = i & 31;
        int rest = i >> 5;
        int f = rest % NFREQ, h = rest / NFREQ;
        Psm[(tok * 8 + h) * 18 + f] =
            g_P[(((size_t)(b * HEADS + h)) * NFREQ + f) * SEQ + n0 + tok];
    }
    __syncthreads();

    const int w = tid >> 5, d = tid & 31;
    const float* __restrict__ vl = g_lin[2];

    for (int it = 0; it < 4; it++) {
        const int tok = w + it * 8;
        const int row = row0 + tok;

        // phase 1: irfft-32 logits for all 8 heads (vectorized f-loads)
        float acc[8];
#pragma unroll
        for (int h = 0; h < 8; h++) {
            const float2* Ph = &Psm[(tok * 8 + h) * 18];
            float2 F0  = Ph[0];
            float2 FN  = Ph[16];
            float2 F[16];
            F[1] = Ph[1];
#pragma unroll
            for (int fp = 0; fp < 7; fp++) {
                float4 vv = *reinterpret_cast<const float4*>(Ph + 2 + 2 * fp);
                F[2 + 2 * fp] = make_float2(vv.x, vv.y);
                F[3 + 2 * fp] = make_float2(vv.z, vv.w);
            }
            float a = F0.x + ((d & 1) ? -FN.x : FN.x);
#pragma unroll
            for (int f = 1; f <= 15; f++) {
                int k2 = (f * d) & 31;
                a += 2.0f * (F[f].x * c32[k2] - F[f].y * s32[k2]);
            }
            acc[h] = a;
        }

        // phase 2: batched max-reduction
        float m[8];
#pragma unroll
        for (int h = 0; h < 8; h++) m[h] = acc[h];
#pragma unroll
        for (int o = 16; o; o >>= 1)
#pragma unroll
            for (int h = 0; h < 8; h++)
                m[h] = fmaxf(m[h], __shfl_xor_sync(0xffffffffu, m[h], o));

        // phase 3: exp
        float e[8];
#pragma unroll
        for (int h = 0; h < 8; h++) e[h] = __expf(acc[h] - m[h]);

        // phase 4: batched sum-reduction
        float ss[8];
#pragma unroll
        for (int h = 0; h < 8; h++) ss[h] = e[h];
#pragma unroll
        for (int o = 16; o; o >>= 1)
#pragma unroll
            for (int h = 0; h < 8; h++)
                ss[h] += __shfl_xor_sync(0xffffffffu, ss[h], o);

        // phase 5: gate + residual; LN stats
        float gh[8];
        float s1 = 0.0f, s2 = 0.0f;
#pragma unroll
        for (int h = 0; h < 8; h++) {
            float p = __fdividef(e[h], ss[h]);
            int c = h * 32 + d;
            float vv = vl[(size_t)row * DIM + c];
            float rv = vin[(size_t)row * DIM + c];
            float g = fmaf(vv, p, rv);
            gh[h] = g; s1 += g; s2 = fmaf(g, g, s2);
        }
#pragma unroll
        for (int o = 16; o; o >>= 1) {
            s1 += __shfl_xor_sync(0xffffffffu, s1, o);
            s2 += __shfl_xor_sync(0xffffffffu, s2, o);
        }
        float mean = s1 * (1.0f / 256.0f);
        float var  = s2 * (1.0f / 256.0f) - mean * mean;
        float inv  = rsqrtf(var + 1e-5f);
#pragma unroll
        for (int h = 0; h < 8; h++) {
            int c = h * 32 + d;
            out[(size_t)row * DIM + c] = (gh[h] - mean) * inv * gamma[c] + beta[c];
        }
    }
}

// =====================================================================================
extern "C" void kernel_launch(void* const* d_in, const int* in_sizes, int n_in,
                              void* d_out, int out_size)
{
    const float* q     = (const float*)d_in[0];
    const float* k     = (const float*)d_in[1];
    const float* v     = (const float*)d_in[2];
    const float* Wq    = (const float*)d_in[3];
    const float* bq    = (const float*)d_in[4];
    const float* Wk    = (const float*)d_in[5];
    const float* bk    = (const float*)d_in[6];
    const float* Wv    = (const float*)d_in[7];
    const float* bv    = (const float*)d_in[8];
    const float* gamma = (const float*)d_in[9];
    const float* beta  = (const float*)d_in[10];
    float* out = (float*)d_out;

    cudaFuncSetAttribute(gemm_qkv_mma, cudaFuncAttributeMaxDynamicSharedMemorySize, SM_GEMM_TOTAL);

    convert_bf16<<<(NX4 + NW4 + 255) / 256, 256>>>(q, k, v, Wq, Wk, Wv);
    gemm_qkv_mma<<<dim3(ROWS / BM, DIM / BN, 3), 256, SM_GEMM_TOTAL>>>(bq, bk, bv);
    fft_conv<<<dim3(NFREQ, BH), 256>>>();
    epilogue<<<ROWS / 32, 256>>>(v, gamma, beta, out);
}